// round 2
// baseline (speedup 1.0000x reference)
#include <cuda_runtime.h>
#include <math.h>

#define HID   128
#define NMAX  100000
#define TE    64     // edges per tile in edge kernel
#define TN    64     // nodes per tile in node kernel

// Scratch (static device globals — no runtime allocation).
__device__ float g_A[(size_t)NMAX * HID];   // per-node dst term: x_i*(w1a-w1b)+b1
__device__ float g_B[(size_t)NMAX * HID];   // per-node src term: x_j*w1b
__device__ int   g_AGG[(size_t)NMAX * HID]; // relu(segment_max) as float bits

// ---------------------------------------------------------------------------
// K1: per-node precompute of layer-1 terms + zero the aggregation buffer.
// msg_in@w1+b1 = x_i·(w1[0:3]-w1[3:6]) + x_j·w1[3:6] + b1
// ---------------------------------------------------------------------------
__global__ void k_node_pre(const float* __restrict__ x,
                           const float* __restrict__ w1,
                           const float* __restrict__ b1, int n)
{
    int idx = blockIdx.x * 256 + threadIdx.x;
    if (idx >= n * HID) return;
    int i = idx >> 7;
    int c = idx & 127;
    float x0 = x[i*3+0], x1 = x[i*3+1], x2 = x[i*3+2];
    float wb0 = w1[3*HID+c], wb1 = w1[4*HID+c], wb2 = w1[5*HID+c];
    float wa0 = w1[0*HID+c] - wb0;
    float wa1 = w1[1*HID+c] - wb1;
    float wa2 = w1[2*HID+c] - wb2;
    g_B[idx] = x0*wb0 + x1*wb1 + x2*wb2;
    g_A[idx] = x0*wa0 + x1*wa1 + x2*wa2 + b1[c];
    g_AGG[idx] = 0;   // float 0.0f bit pattern; valid init for max(relu(h))
}

// ---------------------------------------------------------------------------
// K2: per-edge  h = relu(A[dst]+B[src]) @ w2 + b2 ;  atomicMax(relu(h)) -> AGG
// Block: 256 threads, tile of 64 edges. w2 (64KB) + relu1^T (32KB) in smem.
// Thread (tx,ty): tx in [0,16) -> 8 output channels, ty in [0,16) -> 4 edges.
// ---------------------------------------------------------------------------
__global__ void __launch_bounds__(256, 2)
k_edge(const int* __restrict__ ei, long long E,
       const float* __restrict__ w2, const float* __restrict__ b2)
{
    extern __shared__ float sm[];
    float* sw2 = sm;              // [128][128] row-major (k, c)
    float* sr1 = sm + HID * HID;  // [128][TE]  relu1 transposed (k, e)
    __shared__ int sdst[TE];

    int tid = threadIdx.x;
    long long tile0 = (long long)blockIdx.x * TE;

    // Load w2 into smem (16384 floats = 4096 float4)
    {
        const float4* gv = (const float4*)w2;
        float4* sv = (float4*)sw2;
        #pragma unroll
        for (int i = 0; i < 16; i++) sv[tid + i*256] = gv[tid + i*256];
    }

    // Gather A[dst]+B[src], relu, store transposed. 4 threads per edge.
    {
        int e = tid & 63;
        int q = tid >> 6;              // quarter of the 128-dim row
        long long eg = tile0 + e;
        if (eg < E) {
            int s = ei[eg];            // int32 edge_index (JAX x64 disabled)
            int d = ei[E + eg];
            if (q == 0) sdst[e] = d;
            const float4* Av = (const float4*)(g_A + (size_t)d * HID);
            const float4* Bv = (const float4*)(g_B + (size_t)s * HID);
            #pragma unroll
            for (int j = 0; j < 8; j++) {
                float4 a = Av[q*8 + j];
                float4 b = Bv[q*8 + j];
                int k = q*32 + j*4;
                sr1[(k+0)*TE + e] = fmaxf(a.x + b.x, 0.f);
                sr1[(k+1)*TE + e] = fmaxf(a.y + b.y, 0.f);
                sr1[(k+2)*TE + e] = fmaxf(a.z + b.z, 0.f);
                sr1[(k+3)*TE + e] = fmaxf(a.w + b.w, 0.f);
            }
        } else {
            if (q == 0) sdst[e] = 0;
            #pragma unroll
            for (int j = 0; j < 8; j++) {
                int k = q*32 + j*4;
                sr1[(k+0)*TE + e] = 0.f; sr1[(k+1)*TE + e] = 0.f;
                sr1[(k+2)*TE + e] = 0.f; sr1[(k+3)*TE + e] = 0.f;
            }
        }
    }
    __syncthreads();

    int tx = tid & 15;
    int ty = tid >> 4;
    float acc[4][8];
    #pragma unroll
    for (int j = 0; j < 4; j++)
        #pragma unroll
        for (int c = 0; c < 8; c++) acc[j][c] = 0.f;

    const float* r1p = sr1 + ty * 4;
    const float* w2p = sw2 + tx * 8;
    #pragma unroll 4
    for (int k = 0; k < HID; k++) {
        float4 r  = *(const float4*)(r1p + k*TE);
        float4 wA = *(const float4*)(w2p + k*HID);
        float4 wB = *(const float4*)(w2p + k*HID + 4);
        float rr[4] = {r.x, r.y, r.z, r.w};
        float ww[8] = {wA.x, wA.y, wA.z, wA.w, wB.x, wB.y, wB.z, wB.w};
        #pragma unroll
        for (int j = 0; j < 4; j++)
            #pragma unroll
            for (int c = 0; c < 8; c++)
                acc[j][c] = fmaf(rr[j], ww[c], acc[j][c]);
    }

    float bb[8];
    #pragma unroll
    for (int c = 0; c < 8; c++) bb[c] = b2[tx*8 + c];

    #pragma unroll
    for (int j = 0; j < 4; j++) {
        int el = ty*4 + j;
        if (tile0 + el < E) {
            int d = sdst[el];
            int* ap = g_AGG + (size_t)d * HID + tx * 8;
            #pragma unroll
            for (int c = 0; c < 8; c++) {
                float v = fmaxf(acc[j][c] + bb[c], 0.f);
                atomicMax(ap + c, __float_as_int(v));  // non-neg float bits order as int
            }
        }
    }
}

// ---------------------------------------------------------------------------
// K3: per-node tail.
//  enc = AGG @ w3 + b3        (AGG is already relu(segment_max))
//  t   = relu(enc @ w4 + b4)
//  dec = t @ w5 + b5          (128 -> 3)
//  out = pos + 0.1*tanh(dec)
// Tile of 64 nodes; w3,w4 in smem; activation tile reused for enc^T.
// ---------------------------------------------------------------------------
__global__ void __launch_bounds__(256, 1)
k_node_post(const float* __restrict__ pos,
            const float* __restrict__ w3, const float* __restrict__ b3,
            const float* __restrict__ w4, const float* __restrict__ b4,
            const float* __restrict__ w5, const float* __restrict__ b5,
            float* __restrict__ out, int n)
{
    extern __shared__ float sm[];
    float* sw3 = sm;                // 16384
    float* sw4 = sm + 16384;        // 16384
    float* sx  = sm + 32768;        // 8192: [k][node] (agg^T, then enc^T)

    int tid = threadIdx.x;
    int n0 = blockIdx.x * TN;

    {
        const float4* g3 = (const float4*)w3;
        const float4* g4 = (const float4*)w4;
        float4* s3 = (float4*)sw3;
        float4* s4 = (float4*)sw4;
        #pragma unroll
        for (int i = 0; i < 16; i++) {
            s3[tid + i*256] = g3[tid + i*256];
            s4[tid + i*256] = g4[tid + i*256];
        }
    }

    // load AGG tile transposed
    {
        int e = tid & 63, q = tid >> 6;
        int node = n0 + e;
        if (node < n) {
            const float4* Gv = (const float4*)((const float*)g_AGG + (size_t)node * HID);
            #pragma unroll
            for (int j = 0; j < 8; j++) {
                float4 a = Gv[q*8 + j];
                int k = q*32 + j*4;
                sx[(k+0)*TN + e] = a.x; sx[(k+1)*TN + e] = a.y;
                sx[(k+2)*TN + e] = a.z; sx[(k+3)*TN + e] = a.w;
            }
        } else {
            #pragma unroll
            for (int j = 0; j < 8; j++) {
                int k = q*32 + j*4;
                sx[(k+0)*TN + e] = 0.f; sx[(k+1)*TN + e] = 0.f;
                sx[(k+2)*TN + e] = 0.f; sx[(k+3)*TN + e] = 0.f;
            }
        }
    }
    __syncthreads();

    int tx = tid & 15;
    int ty = tid >> 4;
    float acc[4][8];
    #pragma unroll
    for (int j = 0; j < 4; j++)
        #pragma unroll
        for (int c = 0; c < 8; c++) acc[j][c] = 0.f;

    // GEMM1: enc = agg @ w3
    {
        const float* rp = sx + ty*4;
        const float* wp = sw3 + tx*8;
        #pragma unroll 4
        for (int k = 0; k < HID; k++) {
            float4 r  = *(const float4*)(rp + k*TN);
            float4 wA = *(const float4*)(wp + k*HID);
            float4 wB = *(const float4*)(wp + k*HID + 4);
            float rr[4] = {r.x, r.y, r.z, r.w};
            float ww[8] = {wA.x, wA.y, wA.z, wA.w, wB.x, wB.y, wB.z, wB.w};
            #pragma unroll
            for (int j = 0; j < 4; j++)
                #pragma unroll
                for (int c = 0; c < 8; c++)
                    acc[j][c] = fmaf(rr[j], ww[c], acc[j][c]);
        }
    }
    float b3r[8];
    #pragma unroll
    for (int c = 0; c < 8; c++) b3r[c] = b3[tx*8 + c];

    __syncthreads();   // all GEMM1 reads of sx complete
    // store enc^T into sx: row = channel (GEMM2's k), col = node
    #pragma unroll
    for (int c = 0; c < 8; c++)
        #pragma unroll
        for (int j = 0; j < 4; j++)
            sx[(tx*8 + c)*TN + ty*4 + j] = acc[j][c] + b3r[c];
    __syncthreads();

    // GEMM2: t = relu(enc @ w4 + b4)
    #pragma unroll
    for (int j = 0; j < 4; j++)
        #pragma unroll
        for (int c = 0; c < 8; c++) acc[j][c] = 0.f;
    {
        const float* rp = sx + ty*4;
        const float* wp = sw4 + tx*8;
        #pragma unroll 4
        for (int k = 0; k < HID; k++) {
            float4 r  = *(const float4*)(rp + k*TN);
            float4 wA = *(const float4*)(wp + k*HID);
            float4 wB = *(const float4*)(wp + k*HID + 4);
            float rr[4] = {r.x, r.y, r.z, r.w};
            float ww[8] = {wA.x, wA.y, wA.z, wA.w, wB.x, wB.y, wB.z, wB.w};
            #pragma unroll
            for (int j = 0; j < 4; j++)
                #pragma unroll
                for (int c = 0; c < 8; c++)
                    acc[j][c] = fmaf(rr[j], ww[c], acc[j][c]);
        }
    }
    float b4r[8];
    #pragma unroll
    for (int c = 0; c < 8; c++) b4r[c] = b4[tx*8 + c];

    // dec partials: pd[node][d] = sum over this thread's 8 channels
    float pd[4][3];
    #pragma unroll
    for (int j = 0; j < 4; j++) { pd[j][0] = 0.f; pd[j][1] = 0.f; pd[j][2] = 0.f; }
    #pragma unroll
    for (int c = 0; c < 8; c++) {
        int cg = tx*8 + c;
        float w50 = w5[cg*3 + 0], w51 = w5[cg*3 + 1], w52 = w5[cg*3 + 2];
        #pragma unroll
        for (int j = 0; j < 4; j++) {
            float t = fmaxf(acc[j][c] + b4r[c], 0.f);
            pd[j][0] = fmaf(t, w50, pd[j][0]);
            pd[j][1] = fmaf(t, w51, pd[j][1]);
            pd[j][2] = fmaf(t, w52, pd[j][2]);
        }
    }
    // butterfly reduce across the 16 tx lanes (lane = (ty&1)*16 + tx; xor 1,2,4,8
    // mixes only tx bits)
    #pragma unroll
    for (int o = 8; o >= 1; o >>= 1)
        #pragma unroll
        for (int j = 0; j < 4; j++)
            #pragma unroll
            for (int d = 0; d < 3; d++)
                pd[j][d] += __shfl_xor_sync(0xffffffffu, pd[j][d], o);

    if (tx == 0) {
        float b50 = b5[0], b51 = b5[1], b52 = b5[2];
        #pragma unroll
        for (int j = 0; j < 4; j++) {
            int nd = n0 + ty*4 + j;
            if (nd < n) {
                out[nd*3 + 0] = pos[nd*3 + 0] + 0.1f * tanhf(pd[j][0] + b50);
                out[nd*3 + 1] = pos[nd*3 + 1] + 0.1f * tanhf(pd[j][1] + b51);
                out[nd*3 + 2] = pos[nd*3 + 2] + 0.1f * tanhf(pd[j][2] + b52);
            }
        }
    }
}

// ---------------------------------------------------------------------------
extern "C" void kernel_launch(void* const* d_in, const int* in_sizes, int n_in,
                              void* d_out, int out_size)
{
    const float* x   = (const float*)d_in[0];
    const float* pos = (const float*)d_in[1];
    const int*   ei  = (const int*)d_in[2];   // int32 (JAX default x64-disabled)
    const float* w1 = (const float*)d_in[3];
    const float* b1 = (const float*)d_in[4];
    const float* w2 = (const float*)d_in[5];
    const float* b2 = (const float*)d_in[6];
    const float* w3 = (const float*)d_in[7];
    const float* b3 = (const float*)d_in[8];
    const float* w4 = (const float*)d_in[9];
    const float* b4 = (const float*)d_in[10];
    const float* w5 = (const float*)d_in[11];
    const float* b5 = (const float*)d_in[12];
    float* out = (float*)d_out;

    int       n = in_sizes[0] / 3;      // 100000
    long long E = in_sizes[2] / 2;      // 1600000

    (void)n_in; (void)out_size;

    const int EDGE_SMEM = (HID*HID + HID*TE) * (int)sizeof(float);       // 98304
    const int NODE_SMEM = (2*HID*HID + HID*TN) * (int)sizeof(float);     // 163840
    cudaFuncSetAttribute(k_edge, cudaFuncAttributeMaxDynamicSharedMemorySize, EDGE_SMEM);
    cudaFuncSetAttribute(k_node_post, cudaFuncAttributeMaxDynamicSharedMemorySize, NODE_SMEM);

    int gpre = (n * HID + 255) / 256;
    k_node_pre<<<gpre, 256>>>(x, w1, b1, n);

    int gedge = (int)((E + TE - 1) / TE);
    k_edge<<<gedge, 256, EDGE_SMEM>>>(ei, E, w2, b2);

    int gnode = (n + TN - 1) / TN;
    k_node_post<<<gnode, 256, NODE_SMEM>>>(pos, w3, b3, w4, b4, w5, b5, out, n);
}

// round 3
// speedup vs baseline: 1.7904x; 1.7904x over previous
#include <cuda_runtime.h>
#include <math.h>

#define HID   128
#define NMAX  100000
#define TE    128    // edges per tile in edge kernel
#define TN    64     // nodes per tile in node kernel

typedef unsigned long long ull;

// Scratch (static device globals — no runtime allocation).
__device__ float g_A[(size_t)NMAX * HID];   // per-node dst term: x_i*(w1a-w1b)+b1
__device__ float g_B[(size_t)NMAX * HID];   // per-node src term: x_j*w1b
__device__ int   g_AGG[(size_t)NMAX * HID]; // relu(segment_max) as float bits

// ---- packed fp32x2 helpers (sm_103a FFMA2 path) ----------------------------
__device__ __forceinline__ ull pack2(float lo, float hi) {
    ull r; asm("mov.b64 %0, {%1, %2};" : "=l"(r) : "f"(lo), "f"(hi)); return r;
}
__device__ __forceinline__ void fma2(ull& d, ull a, ull b) {
    asm("fma.rn.f32x2 %0, %1, %2, %0;" : "+l"(d) : "l"(a), "l"(b));
}
__device__ __forceinline__ float2 unpack2(ull v) {
    float2 r; asm("mov.b64 {%0, %1}, %2;" : "=f"(r.x), "=f"(r.y) : "l"(v)); return r;
}

// ---------------------------------------------------------------------------
// K1: per-node precompute of layer-1 terms + zero the aggregation buffer.
// msg_in@w1+b1 = x_i·(w1[0:3]-w1[3:6]) + x_j·w1[3:6] + b1
// ---------------------------------------------------------------------------
__global__ void k_node_pre(const float* __restrict__ x,
                           const float* __restrict__ w1,
                           const float* __restrict__ b1, int n)
{
    int idx = blockIdx.x * 256 + threadIdx.x;
    if (idx >= n * HID) return;
    int i = idx >> 7;
    int c = idx & 127;
    float x0 = x[i*3+0], x1 = x[i*3+1], x2 = x[i*3+2];
    float wb0 = w1[3*HID+c], wb1 = w1[4*HID+c], wb2 = w1[5*HID+c];
    float wa0 = w1[0*HID+c] - wb0;
    float wa1 = w1[1*HID+c] - wb1;
    float wa2 = w1[2*HID+c] - wb2;
    g_B[idx] = x0*wb0 + x1*wb1 + x2*wb2;
    g_A[idx] = x0*wa0 + x1*wa1 + x2*wa2 + b1[c];
    g_AGG[idx] = 0;   // float 0.0f bit pattern; valid init for max(relu(h))
}

// ---------------------------------------------------------------------------
// K2: per-edge  h = relu(A[dst]+B[src]) @ w2 + b2 ;  atomicMax(relu(h)) -> AGG
// 256 threads, tile of 128 edges. w2 (64KB) + relu1^T (64KB) in smem.
// Thread (tx,ty): tx in [0,16) -> 8 channels, ty in [0,16) -> 8 edges.
// Inner product uses packed fma.rn.f32x2 (channel pairs).
// ---------------------------------------------------------------------------
__global__ void __launch_bounds__(256, 1)
k_edge(const int* __restrict__ ei, long long E,
       const float* __restrict__ w2, const float* __restrict__ b2)
{
    extern __shared__ float sm[];
    float* sw2 = sm;              // [128][128] row-major (k, c)
    float* sr1 = sm + HID * HID;  // [128][TE]  relu1 transposed (k, e)
    __shared__ int sdst[TE];

    int tid = threadIdx.x;
    long long tile0 = (long long)blockIdx.x * TE;

    // Load w2 into smem (16384 floats = 4096 float4)
    {
        const float4* gv = (const float4*)w2;
        float4* sv = (float4*)sw2;
        #pragma unroll
        for (int i = 0; i < 16; i++) sv[tid + i*256] = gv[tid + i*256];
    }

    // Gather A[dst]+B[src], relu, store transposed. 2 threads per edge.
    {
        int e = tid >> 1;
        int h = tid & 1;              // half of the 128-dim row
        long long eg = tile0 + e;
        if (eg < E) {
            int s = ei[eg];           // int32 edge_index
            int d = ei[E + eg];
            if (h == 0) sdst[e] = d;
            const float4* Av = (const float4*)(g_A + (size_t)d * HID) + h*16;
            const float4* Bv = (const float4*)(g_B + (size_t)s * HID) + h*16;
            #pragma unroll 4
            for (int j = 0; j < 16; j++) {
                float4 a = Av[j];
                float4 b = Bv[j];
                int k = h*64 + j*4;
                sr1[(k+0)*TE + e] = fmaxf(a.x + b.x, 0.f);
                sr1[(k+1)*TE + e] = fmaxf(a.y + b.y, 0.f);
                sr1[(k+2)*TE + e] = fmaxf(a.z + b.z, 0.f);
                sr1[(k+3)*TE + e] = fmaxf(a.w + b.w, 0.f);
            }
        } else {
            if (h == 0) sdst[e] = -1;
            #pragma unroll 4
            for (int j = 0; j < 16; j++) {
                int k = h*64 + j*4;
                sr1[(k+0)*TE + e] = 0.f; sr1[(k+1)*TE + e] = 0.f;
                sr1[(k+2)*TE + e] = 0.f; sr1[(k+3)*TE + e] = 0.f;
            }
        }
    }
    __syncthreads();

    int tx = tid & 15;
    int ty = tid >> 4;

    ull acc[8][4];
    #pragma unroll
    for (int j = 0; j < 8; j++)
        #pragma unroll
        for (int p = 0; p < 4; p++) acc[j][p] = 0ULL;   // (0.f, 0.f)

    const float* rbase = sr1 + ty * 8;
    const float* wbase = sw2 + tx * 8;
    #pragma unroll 2
    for (int k = 0; k < HID; k++) {
        float4 r03 = *(const float4*)(rbase + k*TE);
        float4 r47 = *(const float4*)(rbase + k*TE + 4);
        ulonglong2 w01 = *(const ulonglong2*)(wbase + k*HID);
        ulonglong2 w23 = *(const ulonglong2*)(wbase + k*HID + 4);
        ull wp[4] = {w01.x, w01.y, w23.x, w23.y};
        float rv[8] = {r03.x, r03.y, r03.z, r03.w, r47.x, r47.y, r47.z, r47.w};
        #pragma unroll
        for (int j = 0; j < 8; j++) {
            ull rp = pack2(rv[j], rv[j]);
            #pragma unroll
            for (int p = 0; p < 4; p++)
                fma2(acc[j][p], rp, wp[p]);
        }
    }

    float bb[8];
    #pragma unroll
    for (int c = 0; c < 8; c++) bb[c] = b2[tx*8 + c];

    #pragma unroll
    for (int j = 0; j < 8; j++) {
        int e = ty*8 + j;
        int d = sdst[e];
        if (d >= 0) {
            int* ap = g_AGG + (size_t)d * HID + tx * 8;
            #pragma unroll
            for (int p = 0; p < 4; p++) {
                float2 v = unpack2(acc[j][p]);
                float v0 = fmaxf(v.x + bb[2*p+0], 0.f);
                float v1 = fmaxf(v.y + bb[2*p+1], 0.f);
                atomicMax(ap + 2*p + 0, __float_as_int(v0));  // non-neg float bits order as int
                atomicMax(ap + 2*p + 1, __float_as_int(v1));
            }
        }
    }
}

// ---------------------------------------------------------------------------
// K3: per-node tail (packed f32x2 GEMMs).
//  enc = AGG @ w3 + b3 ; t = relu(enc @ w4 + b4) ; dec = t @ w5 + b5
//  out = pos + 0.1*tanh(dec)
// ---------------------------------------------------------------------------
__global__ void __launch_bounds__(256, 1)
k_node_post(const float* __restrict__ pos,
            const float* __restrict__ w3, const float* __restrict__ b3,
            const float* __restrict__ w4, const float* __restrict__ b4,
            const float* __restrict__ w5, const float* __restrict__ b5,
            float* __restrict__ out, int n)
{
    extern __shared__ float sm[];
    float* sw3 = sm;                // 16384 floats
    float* sw4 = sm + 16384;        // 16384
    float* sx  = sm + 32768;        // 8192: [k][node] (agg^T, then enc^T)

    int tid = threadIdx.x;
    int n0 = blockIdx.x * TN;

    {
        const float4* g3 = (const float4*)w3;
        const float4* g4 = (const float4*)w4;
        float4* s3 = (float4*)sw3;
        float4* s4 = (float4*)sw4;
        #pragma unroll
        for (int i = 0; i < 16; i++) {
            s3[tid + i*256] = g3[tid + i*256];
            s4[tid + i*256] = g4[tid + i*256];
        }
    }

    // load AGG tile transposed
    {
        int e = tid & 63, q = tid >> 6;
        int node = n0 + e;
        if (node < n) {
            const float4* Gv = (const float4*)((const float*)g_AGG + (size_t)node * HID);
            #pragma unroll
            for (int j = 0; j < 8; j++) {
                float4 a = Gv[q*8 + j];
                int k = q*32 + j*4;
                sx[(k+0)*TN + e] = a.x; sx[(k+1)*TN + e] = a.y;
                sx[(k+2)*TN + e] = a.z; sx[(k+3)*TN + e] = a.w;
            }
        } else {
            #pragma unroll
            for (int j = 0; j < 8; j++) {
                int k = q*32 + j*4;
                sx[(k+0)*TN + e] = 0.f; sx[(k+1)*TN + e] = 0.f;
                sx[(k+2)*TN + e] = 0.f; sx[(k+3)*TN + e] = 0.f;
            }
        }
    }
    __syncthreads();

    int tx = tid & 15;
    int ty = tid >> 4;

    ull acc[4][4];
    #pragma unroll
    for (int j = 0; j < 4; j++)
        #pragma unroll
        for (int p = 0; p < 4; p++) acc[j][p] = 0ULL;

    // GEMM1: enc = agg @ w3
    {
        const float* rp = sx + ty*4;
        const float* wp0 = sw3 + tx*8;
        #pragma unroll 4
        for (int k = 0; k < HID; k++) {
            float4 r  = *(const float4*)(rp + k*TN);
            ulonglong2 w01 = *(const ulonglong2*)(wp0 + k*HID);
            ulonglong2 w23 = *(const ulonglong2*)(wp0 + k*HID + 4);
            ull wpk[4] = {w01.x, w01.y, w23.x, w23.y};
            float rv[4] = {r.x, r.y, r.z, r.w};
            #pragma unroll
            for (int j = 0; j < 4; j++) {
                ull rr = pack2(rv[j], rv[j]);
                #pragma unroll
                for (int p = 0; p < 4; p++)
                    fma2(acc[j][p], rr, wpk[p]);
            }
        }
    }
    float b3r[8];
    #pragma unroll
    for (int c = 0; c < 8; c++) b3r[c] = b3[tx*8 + c];

    __syncthreads();   // all GEMM1 reads of sx complete
    // store enc^T into sx: row = channel (GEMM2's k), col = node
    #pragma unroll
    for (int p = 0; p < 4; p++)
        #pragma unroll
        for (int j = 0; j < 4; j++) {
            float2 v = unpack2(acc[j][p]);
            sx[(tx*8 + 2*p + 0)*TN + ty*4 + j] = v.x + b3r[2*p+0];
            sx[(tx*8 + 2*p + 1)*TN + ty*4 + j] = v.y + b3r[2*p+1];
        }
    __syncthreads();

    // GEMM2: pre-act of (enc @ w4 + b4)
    #pragma unroll
    for (int j = 0; j < 4; j++)
        #pragma unroll
        for (int p = 0; p < 4; p++) acc[j][p] = 0ULL;
    {
        const float* rp = sx + ty*4;
        const float* wp0 = sw4 + tx*8;
        #pragma unroll 4
        for (int k = 0; k < HID; k++) {
            float4 r  = *(const float4*)(rp + k*TN);
            ulonglong2 w01 = *(const ulonglong2*)(wp0 + k*HID);
            ulonglong2 w23 = *(const ulonglong2*)(wp0 + k*HID + 4);
            ull wpk[4] = {w01.x, w01.y, w23.x, w23.y};
            float rv[4] = {r.x, r.y, r.z, r.w};
            #pragma unroll
            for (int j = 0; j < 4; j++) {
                ull rr = pack2(rv[j], rv[j]);
                #pragma unroll
                for (int p = 0; p < 4; p++)
                    fma2(acc[j][p], rr, wpk[p]);
            }
        }
    }
    float b4r[8];
    #pragma unroll
    for (int c = 0; c < 8; c++) b4r[c] = b4[tx*8 + c];

    float ac[4][8];
    #pragma unroll
    for (int j = 0; j < 4; j++)
        #pragma unroll
        for (int p = 0; p < 4; p++) {
            float2 v = unpack2(acc[j][p]);
            ac[j][2*p+0] = v.x;
            ac[j][2*p+1] = v.y;
        }

    // dec partials: pd[node][d] = sum over this thread's 8 channels
    float pd[4][3];
    #pragma unroll
    for (int j = 0; j < 4; j++) { pd[j][0] = 0.f; pd[j][1] = 0.f; pd[j][2] = 0.f; }
    #pragma unroll
    for (int c = 0; c < 8; c++) {
        int cg = tx*8 + c;
        float w50 = w5[cg*3 + 0], w51 = w5[cg*3 + 1], w52 = w5[cg*3 + 2];
        #pragma unroll
        for (int j = 0; j < 4; j++) {
            float t = fmaxf(ac[j][c] + b4r[c], 0.f);
            pd[j][0] = fmaf(t, w50, pd[j][0]);
            pd[j][1] = fmaf(t, w51, pd[j][1]);
            pd[j][2] = fmaf(t, w52, pd[j][2]);
        }
    }
    // butterfly reduce across the 16 tx lanes (lane = (ty&1)*16 + tx)
    #pragma unroll
    for (int o = 8; o >= 1; o >>= 1)
        #pragma unroll
        for (int j = 0; j < 4; j++)
            #pragma unroll
            for (int d = 0; d < 3; d++)
                pd[j][d] += __shfl_xor_sync(0xffffffffu, pd[j][d], o);

    if (tx == 0) {
        float b50 = b5[0], b51 = b5[1], b52 = b5[2];
        #pragma unroll
        for (int j = 0; j < 4; j++) {
            int nd = n0 + ty*4 + j;
            if (nd < n) {
                out[nd*3 + 0] = pos[nd*3 + 0] + 0.1f * tanhf(pd[j][0] + b50);
                out[nd*3 + 1] = pos[nd*3 + 1] + 0.1f * tanhf(pd[j][1] + b51);
                out[nd*3 + 2] = pos[nd*3 + 2] + 0.1f * tanhf(pd[j][2] + b52);
            }
        }
    }
}

// ---------------------------------------------------------------------------
extern "C" void kernel_launch(void* const* d_in, const int* in_sizes, int n_in,
                              void* d_out, int out_size)
{
    const float* x   = (const float*)d_in[0];
    const float* pos = (const float*)d_in[1];
    const int*   ei  = (const int*)d_in[2];   // int32 (JAX default x64-disabled)
    const float* w1 = (const float*)d_in[3];
    const float* b1 = (const float*)d_in[4];
    const float* w2 = (const float*)d_in[5];
    const float* b2 = (const float*)d_in[6];
    const float* w3 = (const float*)d_in[7];
    const float* b3 = (const float*)d_in[8];
    const float* w4 = (const float*)d_in[9];
    const float* b4 = (const float*)d_in[10];
    const float* w5 = (const float*)d_in[11];
    const float* b5 = (const float*)d_in[12];
    float* out = (float*)d_out;

    int       n = in_sizes[0] / 3;      // 100000
    long long E = in_sizes[2] / 2;      // 1600000

    (void)n_in; (void)out_size;

    const int EDGE_SMEM = (HID*HID + HID*TE) * (int)sizeof(float);       // 131072
    const int NODE_SMEM = (2*HID*HID + HID*TN) * (int)sizeof(float);     // 163840
    cudaFuncSetAttribute(k_edge, cudaFuncAttributeMaxDynamicSharedMemorySize, EDGE_SMEM);
    cudaFuncSetAttribute(k_node_post, cudaFuncAttributeMaxDynamicSharedMemorySize, NODE_SMEM);

    int gpre = (n * HID + 255) / 256;
    k_node_pre<<<gpre, 256>>>(x, w1, b1, n);

    int gedge = (int)((E + TE - 1) / TE);
    k_edge<<<gedge, 256, EDGE_SMEM>>>(ei, E, w2, b2);

    int gnode = (n + TN - 1) / TN;
    k_node_post<<<gnode, 256, NODE_SMEM>>>(pos, w3, b3, w4, b4, w5, b5, out, n);
}

// round 5
// speedup vs baseline: 4.1439x; 2.3145x over previous
#include <cuda_runtime.h>
#include <cuda_bf16.h>
#include <cstdint>
#include <math.h>

#define HID   128
#define NMAX  100000
#define TE    128    // edges per tile in edge kernel
#define TN    64     // nodes per tile in node kernel
#define LDW   136    // bf16 row stride in edge-kernel smem (272B)

typedef unsigned long long ull;
typedef unsigned int u32;

// Scratch (static device globals — no runtime allocation).
__device__ float g_A[(size_t)NMAX * HID];   // per-node dst term: x_i*(w1a-w1b)+b1
__device__ float g_B[(size_t)NMAX * HID];   // per-node src term: x_j*w1b
__device__ int   g_AGG[(size_t)NMAX * HID]; // relu(segment_max) as float bits

// ---- packed fp32x2 helpers (sm_103a FFMA2 path, node tail) -----------------
__device__ __forceinline__ ull pack2(float lo, float hi) {
    ull r; asm("mov.b64 %0, {%1, %2};" : "=l"(r) : "f"(lo), "f"(hi)); return r;
}
__device__ __forceinline__ void fma2(ull& d, ull a, ull b) {
    asm("fma.rn.f32x2 %0, %1, %2, %0;" : "+l"(d) : "l"(a), "l"(b));
}
__device__ __forceinline__ float2 unpack2(ull v) {
    float2 r; asm("mov.b64 {%0, %1}, %2;" : "=f"(r.x), "=f"(r.y) : "l"(v)); return r;
}

// ---- bf16 mma helpers ------------------------------------------------------
__device__ __forceinline__ u32 smaddr(const void* p) {
    return (u32)__cvta_generic_to_shared(p);
}
__device__ __forceinline__ void ldsm_x4(u32* r, u32 a) {
    asm volatile("ldmatrix.sync.aligned.m8n8.x4.shared.b16 {%0,%1,%2,%3}, [%4];"
        : "=r"(r[0]), "=r"(r[1]), "=r"(r[2]), "=r"(r[3]) : "r"(a));
}
__device__ __forceinline__ void ldsm_x4_t(u32* r, u32 a) {
    asm volatile("ldmatrix.sync.aligned.m8n8.x4.trans.shared.b16 {%0,%1,%2,%3}, [%4];"
        : "=r"(r[0]), "=r"(r[1]), "=r"(r[2]), "=r"(r[3]) : "r"(a));
}
__device__ __forceinline__ void mma16816(float* c, const u32* a, u32 b0, u32 b1) {
    asm volatile("mma.sync.aligned.m16n8k16.row.col.f32.bf16.bf16.f32 "
        "{%0,%1,%2,%3}, {%4,%5,%6,%7}, {%8,%9}, {%0,%1,%2,%3};"
        : "+f"(c[0]), "+f"(c[1]), "+f"(c[2]), "+f"(c[3])
        : "r"(a[0]), "r"(a[1]), "r"(a[2]), "r"(a[3]), "r"(b0), "r"(b1));
}
__device__ __forceinline__ u32 f2bf2(float lo, float hi) {
    __nv_bfloat162 h2 = __floats2bfloat162_rn(lo, hi);
    return *reinterpret_cast<u32*>(&h2);
}

// ---------------------------------------------------------------------------
// K1: per-node precompute of layer-1 terms + zero the aggregation buffer.
// ---------------------------------------------------------------------------
__global__ void k_node_pre(const float* __restrict__ x,
                           const float* __restrict__ w1,
                           const float* __restrict__ b1, int n)
{
    int idx = blockIdx.x * 256 + threadIdx.x;
    if (idx >= n * HID) return;
    int i = idx >> 7;
    int c = idx & 127;
    float x0 = x[i*3+0], x1 = x[i*3+1], x2 = x[i*3+2];
    float wb0 = w1[3*HID+c], wb1 = w1[4*HID+c], wb2 = w1[5*HID+c];
    float wa0 = w1[0*HID+c] - wb0;
    float wa1 = w1[1*HID+c] - wb1;
    float wa2 = w1[2*HID+c] - wb2;
    g_B[idx] = x0*wb0 + x1*wb1 + x2*wb2;
    g_A[idx] = x0*wa0 + x1*wa1 + x2*wa2 + b1[c];
    g_AGG[idx] = 0;
}

// ---------------------------------------------------------------------------
// K2: bf16 tensor-core edge kernel.
// smem: sw2 = w2 bf16 [128 k][LDW], sa = relu1 bf16 [128 e][LDW]
// Warp w: edges [(w>>1)*32,+32), channels [(w&1)*64,+64).
// ---------------------------------------------------------------------------
__global__ void __launch_bounds__(256, 2)
k_edge(const int* __restrict__ ei, long long E,
       const float* __restrict__ w2, const float* __restrict__ b2)
{
    extern __shared__ char smraw[];
    __nv_bfloat16* sw2 = (__nv_bfloat16*)smraw;
    __nv_bfloat16* sa  = sw2 + 128 * LDW;
    __shared__ int sdst[TE];

    int tid = threadIdx.x;
    long long tile0 = (long long)blockIdx.x * TE;

    // load w2 -> bf16 smem [k][c]
    {
        const float4* gv = (const float4*)w2;   // 4096 float4
        #pragma unroll
        for (int it = 0; it < 16; it++) {
            int idx = tid + it * 256;
            int k  = idx >> 5;
            int c4 = idx & 31;
            float4 v = gv[idx];
            u32* dp = (u32*)(sw2 + k * LDW + c4 * 4);
            dp[0] = f2bf2(v.x, v.y);
            dp[1] = f2bf2(v.z, v.w);
        }
    }

    // gather relu(A[dst]+B[src]) -> bf16 smem rows, 2 threads/edge
    {
        int e  = tid >> 1;
        int hf = tid & 1;
        long long eg = tile0 + e;
        if (eg < E) {
            int s = ei[eg];
            int d = ei[E + eg];
            if (hf == 0) sdst[e] = d;
            const float4* Av = (const float4*)(g_A + (size_t)d * HID) + hf*16;
            const float4* Bv = (const float4*)(g_B + (size_t)s * HID) + hf*16;
            #pragma unroll 4
            for (int j = 0; j < 16; j++) {
                float4 a = Av[j];
                float4 b = Bv[j];
                u32* dp = (u32*)(sa + e * LDW + hf*64 + j*4);
                dp[0] = f2bf2(fmaxf(a.x + b.x, 0.f), fmaxf(a.y + b.y, 0.f));
                dp[1] = f2bf2(fmaxf(a.z + b.z, 0.f), fmaxf(a.w + b.w, 0.f));
            }
        } else {
            if (hf == 0) sdst[e] = -1;
            #pragma unroll 4
            for (int j = 0; j < 16; j++) {
                u32* dp = (u32*)(sa + e * LDW + hf*64 + j*4);
                dp[0] = 0u;
                dp[1] = 0u;
            }
        }
    }
    __syncthreads();

    int lane = tid & 31;
    int wid  = tid >> 5;
    int e0   = (wid >> 1) * 32;
    int n0w  = (wid & 1) * 64;

    float acc[2][8][4];
    #pragma unroll
    for (int m = 0; m < 2; m++) {
        #pragma unroll
        for (int t = 0; t < 8; t++) {
            #pragma unroll
            for (int i = 0; i < 4; i++) acc[m][t][i] = 0.f;
        }
    }

    int rsel = lane & 15;
    int csel = (lane >> 4) << 3;

    #pragma unroll
    for (int k0 = 0; k0 < HID; k0 += 16) {
        u32 A0[4];
        u32 A1[4];
        ldsm_x4(A0, smaddr(sa + (e0 +      rsel) * LDW + k0 + csel));
        ldsm_x4(A1, smaddr(sa + (e0 + 16 + rsel) * LDW + k0 + csel));
        #pragma unroll
        for (int t = 0; t < 4; t++) {
            u32 Bf[4];
            ldsm_x4_t(Bf, smaddr(sw2 + (k0 + rsel) * LDW + n0w + t*16 + csel));
            mma16816(acc[0][2*t+0], A0, Bf[0], Bf[1]);
            mma16816(acc[0][2*t+1], A0, Bf[2], Bf[3]);
            mma16816(acc[1][2*t+0], A1, Bf[0], Bf[1]);
            mma16816(acc[1][2*t+1], A1, Bf[2], Bf[3]);
        }
    }

    // epilogue: +b2, relu, atomicMax
    int r0 = lane >> 2;
    int cq = (lane & 3) * 2;
    int dn00 = sdst[e0 + r0];
    int dn01 = sdst[e0 + r0 + 8];
    int dn10 = sdst[e0 + 16 + r0];
    int dn11 = sdst[e0 + 16 + r0 + 8];

    #pragma unroll
    for (int t = 0; t < 8; t++) {
        int c = n0w + t*8 + cq;
        float bb0 = b2[c];
        float bb1 = b2[c+1];
        #pragma unroll
        for (int m = 0; m < 2; m++) {
            int da = (m == 0) ? dn00 : dn10;
            int db = (m == 0) ? dn01 : dn11;
            if (da >= 0) {
                int* ap = g_AGG + (size_t)da * HID;
                atomicMax(ap + c,     __float_as_int(fmaxf(acc[m][t][0] + bb0, 0.f)));
                atomicMax(ap + c + 1, __float_as_int(fmaxf(acc[m][t][1] + bb1, 0.f)));
            }
            if (db >= 0) {
                int* ap = g_AGG + (size_t)db * HID;
                atomicMax(ap + c,     __float_as_int(fmaxf(acc[m][t][2] + bb0, 0.f)));
                atomicMax(ap + c + 1, __float_as_int(fmaxf(acc[m][t][3] + bb1, 0.f)));
            }
        }
    }
}

// ---------------------------------------------------------------------------
// K3: per-node tail (packed f32x2 GEMMs). Same as R3 (proven).
// ---------------------------------------------------------------------------
__global__ void __launch_bounds__(256, 1)
k_node_post(const float* __restrict__ pos,
            const float* __restrict__ w3, const float* __restrict__ b3,
            const float* __restrict__ w4, const float* __restrict__ b4,
            const float* __restrict__ w5, const float* __restrict__ b5,
            float* __restrict__ out, int n)
{
    extern __shared__ char smraw[];
    float* sw3 = (float*)smraw;
    float* sw4 = sw3 + 16384;
    float* sx  = sw3 + 32768;

    int tid = threadIdx.x;
    int n0 = blockIdx.x * TN;

    {
        const float4* g3 = (const float4*)w3;
        const float4* g4 = (const float4*)w4;
        float4* s3 = (float4*)sw3;
        float4* s4 = (float4*)sw4;
        #pragma unroll
        for (int i = 0; i < 16; i++) {
            s3[tid + i*256] = g3[tid + i*256];
            s4[tid + i*256] = g4[tid + i*256];
        }
    }

    {
        int e = tid & 63;
        int q = tid >> 6;
        int node = n0 + e;
        if (node < n) {
            const float4* Gv = (const float4*)((const float*)g_AGG + (size_t)node * HID);
            #pragma unroll
            for (int j = 0; j < 8; j++) {
                float4 a = Gv[q*8 + j];
                int k = q*32 + j*4;
                sx[(k+0)*TN + e] = a.x;
                sx[(k+1)*TN + e] = a.y;
                sx[(k+2)*TN + e] = a.z;
                sx[(k+3)*TN + e] = a.w;
            }
        } else {
            #pragma unroll
            for (int j = 0; j < 8; j++) {
                int k = q*32 + j*4;
                sx[(k+0)*TN + e] = 0.f;
                sx[(k+1)*TN + e] = 0.f;
                sx[(k+2)*TN + e] = 0.f;
                sx[(k+3)*TN + e] = 0.f;
            }
        }
    }
    __syncthreads();

    int tx = tid & 15;
    int ty = tid >> 4;

    ull acc[4][4];
    #pragma unroll
    for (int j = 0; j < 4; j++) {
        #pragma unroll
        for (int p = 0; p < 4; p++) acc[j][p] = 0ULL;
    }

    // GEMM1: enc = agg @ w3
    {
        const float* rp  = sx + ty*4;
        const float* wp0 = sw3 + tx*8;
        #pragma unroll 4
        for (int k = 0; k < HID; k++) {
            float4 r = *(const float4*)(rp + k*TN);
            ulonglong2 w01 = *(const ulonglong2*)(wp0 + k*HID);
            ulonglong2 w23 = *(const ulonglong2*)(wp0 + k*HID + 4);
            ull wpk[4] = {w01.x, w01.y, w23.x, w23.y};
            float rv[4] = {r.x, r.y, r.z, r.w};
            #pragma unroll
            for (int j = 0; j < 4; j++) {
                ull rr = pack2(rv[j], rv[j]);
                #pragma unroll
                for (int p = 0; p < 4; p++) fma2(acc[j][p], rr, wpk[p]);
            }
        }
    }
    float b3r[8];
    #pragma unroll
    for (int c = 0; c < 8; c++) b3r[c] = b3[tx*8 + c];

    __syncthreads();
    #pragma unroll
    for (int p = 0; p < 4; p++) {
        #pragma unroll
        for (int j = 0; j < 4; j++) {
            float2 v = unpack2(acc[j][p]);
            sx[(tx*8 + 2*p + 0)*TN + ty*4 + j] = v.x + b3r[2*p+0];
            sx[(tx*8 + 2*p + 1)*TN + ty*4 + j] = v.y + b3r[2*p+1];
        }
    }
    __syncthreads();

    // GEMM2: pre-act of (enc @ w4 + b4)
    #pragma unroll
    for (int j = 0; j < 4; j++) {
        #pragma unroll
        for (int p = 0; p < 4; p++) acc[j][p] = 0ULL;
    }
    {
        const float* rp  = sx + ty*4;
        const float* wp0 = sw4 + tx*8;
        #pragma unroll 4
        for (int k = 0; k < HID; k++) {
            float4 r = *(const float4*)(rp + k*TN);
            ulonglong2 w01 = *(const ulonglong2*)(wp0 + k*HID);
            ulonglong2 w23 = *(const ulonglong2*)(wp0 + k*HID + 4);
            ull wpk[4] = {w01.x, w01.y, w23.x, w23.y};
            float rv[4] = {r.x, r.y, r.z, r.w};
            #pragma unroll
            for (int j = 0; j < 4; j++) {
                ull rr = pack2(rv[j], rv[j]);
                #pragma unroll
                for (int p = 0; p < 4; p++) fma2(acc[j][p], rr, wpk[p]);
            }
        }
    }
    float b4r[8];
    #pragma unroll
    for (int c = 0; c < 8; c++) b4r[c] = b4[tx*8 + c];

    float ac[4][8];
    #pragma unroll
    for (int j = 0; j < 4; j++) {
        #pragma unroll
        for (int p = 0; p < 4; p++) {
            float2 v = unpack2(acc[j][p]);
            ac[j][2*p+0] = v.x;
            ac[j][2*p+1] = v.y;
        }
    }

    float pd[4][3];
    #pragma unroll
    for (int j = 0; j < 4; j++) {
        pd[j][0] = 0.f; pd[j][1] = 0.f; pd[j][2] = 0.f;
    }
    #pragma unroll
    for (int c = 0; c < 8; c++) {
        int cg = tx*8 + c;
        float w50 = w5[cg*3 + 0];
        float w51 = w5[cg*3 + 1];
        float w52 = w5[cg*3 + 2];
        #pragma unroll
        for (int j = 0; j < 4; j++) {
            float t = fmaxf(ac[j][c] + b4r[c], 0.f);
            pd[j][0] = fmaf(t, w50, pd[j][0]);
            pd[j][1] = fmaf(t, w51, pd[j][1]);
            pd[j][2] = fmaf(t, w52, pd[j][2]);
        }
    }
    #pragma unroll
    for (int o = 8; o >= 1; o >>= 1) {
        #pragma unroll
        for (int j = 0; j < 4; j++) {
            #pragma unroll
            for (int d = 0; d < 3; d++)
                pd[j][d] += __shfl_xor_sync(0xffffffffu, pd[j][d], o);
        }
    }

    if (tx == 0) {
        float b50 = b5[0];
        float b51 = b5[1];
        float b52 = b5[2];
        #pragma unroll
        for (int j = 0; j < 4; j++) {
            int nd = n0 + ty*4 + j;
            if (nd < n) {
                out[nd*3 + 0] = pos[nd*3 + 0] + 0.1f * tanhf(pd[j][0] + b50);
                out[nd*3 + 1] = pos[nd*3 + 1] + 0.1f * tanhf(pd[j][1] + b51);
                out[nd*3 + 2] = pos[nd*3 + 2] + 0.1f * tanhf(pd[j][2] + b52);
            }
        }
    }
}

// ---------------------------------------------------------------------------
extern "C" void kernel_launch(void* const* d_in, const int* in_sizes, int n_in,
                              void* d_out, int out_size)
{
    const float* x   = (const float*)d_in[0];
    const float* pos = (const float*)d_in[1];
    const int*   ei  = (const int*)d_in[2];   // int32 (JAX default x64-disabled)
    const float* w1 = (const float*)d_in[3];
    const float* b1 = (const float*)d_in[4];
    const float* w2 = (const float*)d_in[5];
    const float* b2 = (const float*)d_in[6];
    const float* w3 = (const float*)d_in[7];
    const float* b3 = (const float*)d_in[8];
    const float* w4 = (const float*)d_in[9];
    const float* b4 = (const float*)d_in[10];
    const float* w5 = (const float*)d_in[11];
    const float* b5 = (const float*)d_in[12];
    float* out = (float*)d_out;

    int       n = in_sizes[0] / 3;      // 100000
    long long E = in_sizes[2] / 2;      // 1600000

    (void)n_in;
    (void)out_size;

    const int EDGE_SMEM = 2 * 128 * LDW * (int)sizeof(__nv_bfloat16);    // 69632
    const int NODE_SMEM = (2*HID*HID + HID*TN) * (int)sizeof(float);     // 163840
    cudaFuncSetAttribute(k_edge, cudaFuncAttributeMaxDynamicSharedMemorySize, EDGE_SMEM);
    cudaFuncSetAttribute(k_node_post, cudaFuncAttributeMaxDynamicSharedMemorySize, NODE_SMEM);

    int gpre = (n * HID + 255) / 256;
    k_node_pre<<<gpre, 256>>>(x, w1, b1, n);

    int gedge = (int)((E + TE - 1) / TE);
    k_edge<<<gedge, 256, EDGE_SMEM>>>(ei, E, w2, b2);

    int gnode = (n + TN - 1) / TN;
    k_node_post<<<gnode, 256, NODE_SMEM>>>(pos, w3, b3, w4, b4, w5, b5, out, n);
}

// round 7
// speedup vs baseline: 4.5567x; 1.0996x over previous
#include <cuda_runtime.h>
#include <cuda_bf16.h>
#include <cstdint>
#include <math.h>

#define HID   128
#define NMAX  100000
#define EMAX  1600000
#define TE    128    // edges per tile in edge kernel
#define TN    64     // nodes per tile in node kernel
#define LDW   136    // bf16 row stride in edge-kernel smem
#define LDH   136    // f32 row stride of h-tile in smem

typedef unsigned long long ull;
typedef unsigned int u32;

// Scratch (static device globals — no runtime allocation).
__device__ float g_A[(size_t)NMAX * HID];   // per-node dst term
__device__ float g_B[(size_t)NMAX * HID];   // per-node src term
__device__ int   g_AGG[(size_t)NMAX * HID]; // relu(segment_max) as float bits
__device__ int   g_cnt[NMAX];               // per-dst degree
__device__ int   g_off[NMAX];               // exclusive offsets (consumed as cursors)
__device__ int   g_ssrc[EMAX];              // src sorted by dst
__device__ int   g_sdst[EMAX];              // dst sorted (non-decreasing)

// ---- packed fp32x2 helpers (node tail) -------------------------------------
__device__ __forceinline__ ull pack2(float lo, float hi) {
    ull r; asm("mov.b64 %0, {%1, %2};" : "=l"(r) : "f"(lo), "f"(hi)); return r;
}
__device__ __forceinline__ void fma2(ull& d, ull a, ull b) {
    asm("fma.rn.f32x2 %0, %1, %2, %0;" : "+l"(d) : "l"(a), "l"(b));
}
__device__ __forceinline__ float2 unpack2(ull v) {
    float2 r; asm("mov.b64 {%0, %1}, %2;" : "=f"(r.x), "=f"(r.y) : "l"(v)); return r;
}

// ---- bf16 mma helpers ------------------------------------------------------
__device__ __forceinline__ u32 smaddr(const void* p) {
    return (u32)__cvta_generic_to_shared(p);
}
__device__ __forceinline__ void ldsm_x4(u32* r, u32 a) {
    asm volatile("ldmatrix.sync.aligned.m8n8.x4.shared.b16 {%0,%1,%2,%3}, [%4];"
        : "=r"(r[0]), "=r"(r[1]), "=r"(r[2]), "=r"(r[3]) : "r"(a));
}
__device__ __forceinline__ void ldsm_x4_t(u32* r, u32 a) {
    asm volatile("ldmatrix.sync.aligned.m8n8.x4.trans.shared.b16 {%0,%1,%2,%3}, [%4];"
        : "=r"(r[0]), "=r"(r[1]), "=r"(r[2]), "=r"(r[3]) : "r"(a));
}
__device__ __forceinline__ void mma16816(float* c, const u32* a, u32 b0, u32 b1) {
    asm volatile("mma.sync.aligned.m16n8k16.row.col.f32.bf16.bf16.f32 "
        "{%0,%1,%2,%3}, {%4,%5,%6,%7}, {%8,%9}, {%0,%1,%2,%3};"
        : "+f"(c[0]), "+f"(c[1]), "+f"(c[2]), "+f"(c[3])
        : "r"(a[0]), "r"(a[1]), "r"(a[2]), "r"(a[3]), "r"(b0), "r"(b1));
}
__device__ __forceinline__ u32 f2bf2(float lo, float hi) {
    __nv_bfloat162 h2 = __floats2bfloat162_rn(lo, hi);
    return *reinterpret_cast<u32*>(&h2);
}

// ---------------------------------------------------------------------------
// K1: per-node precompute of layer-1 terms + zero AGG + zero degree counters.
// ---------------------------------------------------------------------------
__global__ void k_node_pre(const float* __restrict__ x,
                           const float* __restrict__ w1,
                           const float* __restrict__ b1, int n)
{
    int idx = blockIdx.x * 256 + threadIdx.x;
    if (idx >= n * HID) return;
    int i = idx >> 7;
    int c = idx & 127;
    float x0 = x[i*3+0], x1 = x[i*3+1], x2 = x[i*3+2];
    float wb0 = w1[3*HID+c], wb1 = w1[4*HID+c], wb2 = w1[5*HID+c];
    float wa0 = w1[0*HID+c] - wb0;
    float wa1 = w1[1*HID+c] - wb1;
    float wa2 = w1[2*HID+c] - wb2;
    g_B[idx] = x0*wb0 + x1*wb1 + x2*wb2;
    g_A[idx] = x0*wa0 + x1*wa1 + x2*wa2 + b1[c];
    g_AGG[idx] = 0;
    if (c == 0) g_cnt[i] = 0;
}

// ---------------------------------------------------------------------------
// S1: histogram of dst degrees.
// ---------------------------------------------------------------------------
__global__ void k_hist(const int* __restrict__ ei, int E)
{
    int e = blockIdx.x * 256 + threadIdx.x;
    if (e < E) atomicAdd(&g_cnt[ei[E + e]], 1);
}

// ---------------------------------------------------------------------------
// S2: single-block exclusive scan of g_cnt -> g_off (warp-shfl based).
// 1024 threads = 32 warps.
// ---------------------------------------------------------------------------
__global__ void __launch_bounds__(1024, 1) k_scan(int n)
{
    __shared__ int wsum[32];
    __shared__ int carry;
    int tid  = threadIdx.x;
    int lane = tid & 31;
    int w    = tid >> 5;
    if (tid == 0) carry = 0;
    __syncthreads();

    for (int base = 0; base < n; base += 1024) {
        int i = base + tid;
        int v = (i < n) ? g_cnt[i] : 0;
        // warp inclusive scan
        int xv = v;
        #pragma unroll
        for (int off = 1; off < 32; off <<= 1) {
            int y = __shfl_up_sync(0xffffffffu, xv, off);
            if (lane >= off) xv += y;
        }
        if (lane == 31) wsum[w] = xv;
        __syncthreads();
        if (w == 0) {
            int t = wsum[lane];
            #pragma unroll
            for (int off = 1; off < 32; off <<= 1) {
                int y = __shfl_up_sync(0xffffffffu, t, off);
                if (lane >= off) t += y;
            }
            wsum[lane] = t;
        }
        __syncthreads();
        int woff = (w > 0) ? wsum[w - 1] : 0;
        int incl = xv + woff;
        if (i < n) g_off[i] = carry + incl - v;   // exclusive
        __syncthreads();
        if (tid == 0) carry += wsum[31];
        __syncthreads();
    }
}

// ---------------------------------------------------------------------------
// S3: scatter edges into dst-sorted order (g_off consumed as cursors).
// ---------------------------------------------------------------------------
__global__ void k_scatter(const int* __restrict__ ei, int E)
{
    int e = blockIdx.x * 256 + threadIdx.x;
    if (e < E) {
        int s = ei[e];
        int d = ei[E + e];
        int p = atomicAdd(&g_off[d], 1);
        g_ssrc[p] = s;
        g_sdst[p] = d;
    }
}

// ---------------------------------------------------------------------------
// K2: bf16 tensor-core edge kernel over dst-sorted edges.
// smem: sw2 bf16 [128][LDW]  |  union{ sa bf16 [128][LDW], sh f32 [128][LDH] }
// After MMA, h-tile goes to smem; segmented max per channel (warp-uniform
// group boundaries because edges are dst-sorted) -> few coalesced atomics.
// ---------------------------------------------------------------------------
__global__ void __launch_bounds__(256, 2)
k_edge(int E, const float* __restrict__ w2, const float* __restrict__ b2)
{
    extern __shared__ char smraw[];
    __nv_bfloat16* sw2 = (__nv_bfloat16*)smraw;
    __nv_bfloat16* sa  = (__nv_bfloat16*)(smraw + 128 * LDW * 2);
    float*         sh  = (float*)(smraw + 128 * LDW * 2);   // overlays sa
    __shared__ int sdst[TE];

    int tid = threadIdx.x;
    int tile0 = blockIdx.x * TE;

    // load w2 -> bf16 smem [k][c]
    {
        const float4* gv = (const float4*)w2;
        #pragma unroll
        for (int it = 0; it < 16; it++) {
            int idx = tid + it * 256;
            int k  = idx >> 5;
            int c4 = idx & 31;
            float4 v = gv[idx];
            u32* dp = (u32*)(sw2 + k * LDW + c4 * 4);
            dp[0] = f2bf2(v.x, v.y);
            dp[1] = f2bf2(v.z, v.w);
        }
    }

    // gather relu(A[dst]+B[src]) -> bf16 smem rows, 2 threads/edge
    {
        int e  = tid >> 1;
        int hf = tid & 1;
        int eg = tile0 + e;
        if (eg < E) {
            int s = g_ssrc[eg];
            int d = g_sdst[eg];
            if (hf == 0) sdst[e] = d;
            const float4* Av = (const float4*)(g_A + (size_t)d * HID) + hf*16;
            const float4* Bv = (const float4*)(g_B + (size_t)s * HID) + hf*16;
            #pragma unroll 4
            for (int j = 0; j < 16; j++) {
                float4 a = Av[j];
                float4 b = Bv[j];
                u32* dp = (u32*)(sa + e * LDW + hf*64 + j*4);
                dp[0] = f2bf2(fmaxf(a.x + b.x, 0.f), fmaxf(a.y + b.y, 0.f));
                dp[1] = f2bf2(fmaxf(a.z + b.z, 0.f), fmaxf(a.w + b.w, 0.f));
            }
        } else {
            if (hf == 0) sdst[e] = -1;
            #pragma unroll 4
            for (int j = 0; j < 16; j++) {
                u32* dp = (u32*)(sa + e * LDW + hf*64 + j*4);
                dp[0] = 0u;
                dp[1] = 0u;
            }
        }
    }
    __syncthreads();

    int lane = tid & 31;
    int wid  = tid >> 5;
    int e0   = (wid >> 1) * 32;
    int n0w  = (wid & 1) * 64;

    float acc[2][8][4];
    #pragma unroll
    for (int m = 0; m < 2; m++) {
        #pragma unroll
        for (int t = 0; t < 8; t++) {
            #pragma unroll
            for (int i = 0; i < 4; i++) acc[m][t][i] = 0.f;
        }
    }

    int rsel = lane & 15;
    int csel = (lane >> 4) << 3;

    #pragma unroll
    for (int k0 = 0; k0 < HID; k0 += 16) {
        u32 A0[4];
        u32 A1[4];
        ldsm_x4(A0, smaddr(sa + (e0 +      rsel) * LDW + k0 + csel));
        ldsm_x4(A1, smaddr(sa + (e0 + 16 + rsel) * LDW + k0 + csel));
        #pragma unroll
        for (int t = 0; t < 4; t++) {
            u32 Bf[4];
            ldsm_x4_t(Bf, smaddr(sw2 + (k0 + rsel) * LDW + n0w + t*16 + csel));
            mma16816(acc[0][2*t+0], A0, Bf[0], Bf[1]);
            mma16816(acc[0][2*t+1], A0, Bf[2], Bf[3]);
            mma16816(acc[1][2*t+0], A1, Bf[0], Bf[1]);
            mma16816(acc[1][2*t+1], A1, Bf[2], Bf[3]);
        }
    }

    // all warps done reading sa before overlaying with sh
    __syncthreads();

    // store raw h fragments to sh [edge][channel]
    {
        int r0 = lane >> 2;
        int cq = (lane & 3) * 2;
        #pragma unroll
        for (int m = 0; m < 2; m++) {
            int rbase = e0 + m*16 + r0;
            #pragma unroll
            for (int t = 0; t < 8; t++) {
                int c = n0w + t*8 + cq;
                *(float2*)(sh + rbase       * LDH + c) = make_float2(acc[m][t][0], acc[m][t][1]);
                *(float2*)(sh + (rbase + 8) * LDH + c) = make_float2(acc[m][t][2], acc[m][t][3]);
            }
        }
    }
    __syncthreads();

    // segmented max over dst-groups. Thread: channel c over 64 edges.
    // sdst sequence identical across warp lanes -> uniform branches,
    // flush atomics coalesced (32 consecutive channels per warp).
    {
        int c  = tid & 127;
        int eb = (tid >> 7) * 64;
        float bb = b2[c];
        int prev = sdst[eb];
        float mx = sh[eb * LDH + c];
        #pragma unroll 4
        for (int j = 1; j < 64; j++) {
            int d2  = sdst[eb + j];
            float v = sh[(eb + j) * LDH + c];
            if (d2 != prev) {
                if (prev >= 0)
                    atomicMax(g_AGG + (size_t)prev * HID + c,
                              __float_as_int(fmaxf(mx + bb, 0.f)));
                prev = d2;
                mx = v;
            } else {
                mx = fmaxf(mx, v);
            }
        }
        if (prev >= 0)
            atomicMax(g_AGG + (size_t)prev * HID + c,
                      __float_as_int(fmaxf(mx + bb, 0.f)));
    }
}

// ---------------------------------------------------------------------------
// K3: per-node tail (packed f32x2 GEMMs). Unchanged (proven).
// ---------------------------------------------------------------------------
__global__ void __launch_bounds__(256, 1)
k_node_post(const float* __restrict__ pos,
            const float* __restrict__ w3, const float* __restrict__ b3,
            const float* __restrict__ w4, const float* __restrict__ b4,
            const float* __restrict__ w5, const float* __restrict__ b5,
            float* __restrict__ out, int n)
{
    extern __shared__ char smraw[];
    float* sw3 = (float*)smraw;
    float* sw4 = sw3 + 16384;
    float* sx  = sw3 + 32768;

    int tid = threadIdx.x;
    int n0 = blockIdx.x * TN;

    {
        const float4* g3 = (const float4*)w3;
        const float4* g4 = (const float4*)w4;
        float4* s3 = (float4*)sw3;
        float4* s4 = (float4*)sw4;
        #pragma unroll
        for (int i = 0; i < 16; i++) {
            s3[tid + i*256] = g3[tid + i*256];
            s4[tid + i*256] = g4[tid + i*256];
        }
    }

    {
        int e = tid & 63;
        int q = tid >> 6;
        int node = n0 + e;
        if (node < n) {
            const float4* Gv = (const float4*)((const float*)g_AGG + (size_t)node * HID);
            #pragma unroll
            for (int j = 0; j < 8; j++) {
                float4 a = Gv[q*8 + j];
                int k = q*32 + j*4;
                sx[(k+0)*TN + e] = a.x;
                sx[(k+1)*TN + e] = a.y;
                sx[(k+2)*TN + e] = a.z;
                sx[(k+3)*TN + e] = a.w;
            }
        } else {
            #pragma unroll
            for (int j = 0; j < 8; j++) {
                int k = q*32 + j*4;
                sx[(k+0)*TN + e] = 0.f;
                sx[(k+1)*TN + e] = 0.f;
                sx[(k+2)*TN + e] = 0.f;
                sx[(k+3)*TN + e] = 0.f;
            }
        }
    }
    __syncthreads();

    int tx = tid & 15;
    int ty = tid >> 4;

    ull acc[4][4];
    #pragma unroll
    for (int j = 0; j < 4; j++) {
        #pragma unroll
        for (int p = 0; p < 4; p++) acc[j][p] = 0ULL;
    }

    // GEMM1: enc = agg @ w3
    {
        const float* rp  = sx + ty*4;
        const float* wp0 = sw3 + tx*8;
        #pragma unroll 4
        for (int k = 0; k < HID; k++) {
            float4 r = *(const float4*)(rp + k*TN);
            ulonglong2 w01 = *(const ulonglong2*)(wp0 + k*HID);
            ulonglong2 w23 = *(const ulonglong2*)(wp0 + k*HID + 4);
            ull wpk[4] = {w01.x, w01.y, w23.x, w23.y};
            float rv[4] = {r.x, r.y, r.z, r.w};
            #pragma unroll
            for (int j = 0; j < 4; j++) {
                ull rr = pack2(rv[j], rv[j]);
                #pragma unroll
                for (int p = 0; p < 4; p++) fma2(acc[j][p], rr, wpk[p]);
            }
        }
    }
    float b3r[8];
    #pragma unroll
    for (int c = 0; c < 8; c++) b3r[c] = b3[tx*8 + c];

    __syncthreads();
    #pragma unroll
    for (int p = 0; p < 4; p++) {
        #pragma unroll
        for (int j = 0; j < 4; j++) {
            float2 v = unpack2(acc[j][p]);
            sx[(tx*8 + 2*p + 0)*TN + ty*4 + j] = v.x + b3r[2*p+0];
            sx[(tx*8 + 2*p + 1)*TN + ty*4 + j] = v.y + b3r[2*p+1];
        }
    }
    __syncthreads();

    // GEMM2: pre-act of (enc @ w4 + b4)
    #pragma unroll
    for (int j = 0; j < 4; j++) {
        #pragma unroll
        for (int p = 0; p < 4; p++) acc[j][p] = 0ULL;
    }
    {
        const float* rp  = sx + ty*4;
        const float* wp0 = sw4 + tx*8;
        #pragma unroll 4
        for (int k = 0; k < HID; k++) {
            float4 r = *(const float4*)(rp + k*TN);
            ulonglong2 w01 = *(const ulonglong2*)(wp0 + k*HID);
            ulonglong2 w23 = *(const ulonglong2*)(wp0 + k*HID + 4);
            ull wpk[4] = {w01.x, w01.y, w23.x, w23.y};
            float rv[4] = {r.x, r.y, r.z, r.w};
            #pragma unroll
            for (int j = 0; j < 4; j++) {
                ull rr = pack2(rv[j], rv[j]);
                #pragma unroll
                for (int p = 0; p < 4; p++) fma2(acc[j][p], rr, wpk[p]);
            }
        }
    }
    float b4r[8];
    #pragma unroll
    for (int c = 0; c < 8; c++) b4r[c] = b4[tx*8 + c];

    float ac[4][8];
    #pragma unroll
    for (int j = 0; j < 4; j++) {
        #pragma unroll
        for (int p = 0; p < 4; p++) {
            float2 v = unpack2(acc[j][p]);
            ac[j][2*p+0] = v.x;
            ac[j][2*p+1] = v.y;
        }
    }

    float pd[4][3];
    #pragma unroll
    for (int j = 0; j < 4; j++) {
        pd[j][0] = 0.f; pd[j][1] = 0.f; pd[j][2] = 0.f;
    }
    #pragma unroll
    for (int c = 0; c < 8; c++) {
        int cg = tx*8 + c;
        float w50 = w5[cg*3 + 0];
        float w51 = w5[cg*3 + 1];
        float w52 = w5[cg*3 + 2];
        #pragma unroll
        for (int j = 0; j < 4; j++) {
            float t = fmaxf(ac[j][c] + b4r[c], 0.f);
            pd[j][0] = fmaf(t, w50, pd[j][0]);
            pd[j][1] = fmaf(t, w51, pd[j][1]);
            pd[j][2] = fmaf(t, w52, pd[j][2]);
        }
    }
    #pragma unroll
    for (int o = 8; o >= 1; o >>= 1) {
        #pragma unroll
        for (int j = 0; j < 4; j++) {
            #pragma unroll
            for (int d = 0; d < 3; d++)
                pd[j][d] += __shfl_xor_sync(0xffffffffu, pd[j][d], o);
        }
    }

    if (tx == 0) {
        float b50 = b5[0];
        float b51 = b5[1];
        float b52 = b5[2];
        #pragma unroll
        for (int j = 0; j < 4; j++) {
            int nd = n0 + ty*4 + j;
            if (nd < n) {
                out[nd*3 + 0] = pos[nd*3 + 0] + 0.1f * tanhf(pd[j][0] + b50);
                out[nd*3 + 1] = pos[nd*3 + 1] + 0.1f * tanhf(pd[j][1] + b51);
                out[nd*3 + 2] = pos[nd*3 + 2] + 0.1f * tanhf(pd[j][2] + b52);
            }
        }
    }
}

// ---------------------------------------------------------------------------
extern "C" void kernel_launch(void* const* d_in, const int* in_sizes, int n_in,
                              void* d_out, int out_size)
{
    const float* x   = (const float*)d_in[0];
    const float* pos = (const float*)d_in[1];
    const int*   ei  = (const int*)d_in[2];   // int32
    const float* w1 = (const float*)d_in[3];
    const float* b1 = (const float*)d_in[4];
    const float* w2 = (const float*)d_in[5];
    const float* b2 = (const float*)d_in[6];
    const float* w3 = (const float*)d_in[7];
    const float* b3 = (const float*)d_in[8];
    const float* w4 = (const float*)d_in[9];
    const float* b4 = (const float*)d_in[10];
    const float* w5 = (const float*)d_in[11];
    const float* b5 = (const float*)d_in[12];
    float* out = (float*)d_out;

    int n = in_sizes[0] / 3;      // 100000
    int E = in_sizes[2] / 2;      // 1600000

    (void)n_in;
    (void)out_size;

    const int EDGE_SMEM = 128 * LDW * 2 + 128 * LDH * 4;                 // 104448
    const int NODE_SMEM = (2*HID*HID + HID*TN) * (int)sizeof(float);     // 163840
    cudaFuncSetAttribute(k_edge, cudaFuncAttributeMaxDynamicSharedMemorySize, EDGE_SMEM);
    cudaFuncSetAttribute(k_node_post, cudaFuncAttributeMaxDynamicSharedMemorySize, NODE_SMEM);

    int gpre = (n * HID + 255) / 256;
    k_node_pre<<<gpre, 256>>>(x, w1, b1, n);

    int ge = (E + 255) / 256;
    k_hist<<<ge, 256>>>(ei, E);
    k_scan<<<1, 1024>>>(n);
    k_scatter<<<ge, 256>>>(ei, E);

    int gedge = (E + TE - 1) / TE;
    k_edge<<<gedge, 256, EDGE_SMEM>>>(E, w2, b2);

    int gnode = (n + TN - 1) / TN;
    k_node_post<<<gnode, 256, NODE_SMEM>>>(pos, w3, b3, w4, b4, w5, b5, out, n);
}

// round 8
// speedup vs baseline: 6.0161x; 1.3203x over previous
#include <cuda_runtime.h>
#include <cuda_bf16.h>
#include <cstdint>
#include <math.h>

#define HID   128
#define NMAX  100000
#define EMAX  1600000
#define TE    128    // edges per tile in edge kernel
#define TN    64     // nodes per tile in node kernel
#define LDW   136    // bf16 row stride in edge-kernel smem (272B, 16B-aligned rows)

typedef unsigned long long ull;
typedef unsigned int u32;

// Scratch (static device globals — no runtime allocation).
__device__ __nv_bfloat16 g_Abf[(size_t)NMAX * HID];  // per-node dst term (bf16)
__device__ __nv_bfloat16 g_Bbf[(size_t)NMAX * HID];  // per-node src term (bf16)
__device__ __nv_bfloat16 g_w2bf[HID * HID];          // w2 in bf16 [k][c]
__device__ int   g_AGG[(size_t)NMAX * HID]; // relu(segment_max) as float bits
__device__ int   g_cnt[NMAX];               // per-dst degree
__device__ int   g_off[NMAX];               // exclusive offsets (consumed as cursors)
__device__ int   g_ssrc[EMAX];              // src sorted by dst
__device__ int   g_sdst[EMAX];              // dst sorted (non-decreasing)

// ---- packed fp32x2 helpers (node tail) -------------------------------------
__device__ __forceinline__ ull pack2(float lo, float hi) {
    ull r; asm("mov.b64 %0, {%1, %2};" : "=l"(r) : "f"(lo), "f"(hi)); return r;
}
__device__ __forceinline__ void fma2(ull& d, ull a, ull b) {
    asm("fma.rn.f32x2 %0, %1, %2, %0;" : "+l"(d) : "l"(a), "l"(b));
}
__device__ __forceinline__ float2 unpack2(ull v) {
    float2 r; asm("mov.b64 {%0, %1}, %2;" : "=f"(r.x), "=f"(r.y) : "l"(v)); return r;
}

// ---- bf16 helpers ----------------------------------------------------------
__device__ __forceinline__ u32 smaddr(const void* p) {
    return (u32)__cvta_generic_to_shared(p);
}
__device__ __forceinline__ void ldsm_x4(u32* r, u32 a) {
    asm volatile("ldmatrix.sync.aligned.m8n8.x4.shared.b16 {%0,%1,%2,%3}, [%4];"
        : "=r"(r[0]), "=r"(r[1]), "=r"(r[2]), "=r"(r[3]) : "r"(a));
}
__device__ __forceinline__ void ldsm_x4_t(u32* r, u32 a) {
    asm volatile("ldmatrix.sync.aligned.m8n8.x4.trans.shared.b16 {%0,%1,%2,%3}, [%4];"
        : "=r"(r[0]), "=r"(r[1]), "=r"(r[2]), "=r"(r[3]) : "r"(a));
}
__device__ __forceinline__ void mma16816(float* c, const u32* a, u32 b0, u32 b1) {
    asm volatile("mma.sync.aligned.m16n8k16.row.col.f32.bf16.bf16.f32 "
        "{%0,%1,%2,%3}, {%4,%5,%6,%7}, {%8,%9}, {%0,%1,%2,%3};"
        : "+f"(c[0]), "+f"(c[1]), "+f"(c[2]), "+f"(c[3])
        : "r"(a[0]), "r"(a[1]), "r"(a[2]), "r"(a[3]), "r"(b0), "r"(b1));
}
__device__ __forceinline__ u32 f2bf2(float lo, float hi) {
    __nv_bfloat162 h2 = __floats2bfloat162_rn(lo, hi);
    return *reinterpret_cast<u32*>(&h2);
}
// relu(a + b) on packed bf16x2
__device__ __forceinline__ u32 hadd_relu2(u32 ua, u32 ub) {
    __nv_bfloat162 a = *reinterpret_cast<__nv_bfloat162*>(&ua);
    __nv_bfloat162 b = *reinterpret_cast<__nv_bfloat162*>(&ub);
    u32 uz = 0u;
    __nv_bfloat162 z = *reinterpret_cast<__nv_bfloat162*>(&uz);
    __nv_bfloat162 r = __hmax2(__hadd2(a, b), z);
    return *reinterpret_cast<u32*>(&r);
}
__device__ __forceinline__ u32 hmax2u(u32 ua, u32 ub) {
    __nv_bfloat162 a = *reinterpret_cast<__nv_bfloat162*>(&ua);
    __nv_bfloat162 b = *reinterpret_cast<__nv_bfloat162*>(&ub);
    __nv_bfloat162 r = __hmax2(a, b);
    return *reinterpret_cast<u32*>(&r);
}

// ---------------------------------------------------------------------------
// K1: per-node layer-1 terms (bf16) + zero AGG + zero degree counters.
// ---------------------------------------------------------------------------
__global__ void k_node_pre(const float* __restrict__ x,
                           const float* __restrict__ w1,
                           const float* __restrict__ b1, int n)
{
    int idx = blockIdx.x * 256 + threadIdx.x;
    if (idx >= n * HID) return;
    int i = idx >> 7;
    int c = idx & 127;
    float x0 = x[i*3+0], x1 = x[i*3+1], x2 = x[i*3+2];
    float wb0 = w1[3*HID+c], wb1 = w1[4*HID+c], wb2 = w1[5*HID+c];
    float wa0 = w1[0*HID+c] - wb0;
    float wa1 = w1[1*HID+c] - wb1;
    float wa2 = w1[2*HID+c] - wb2;
    g_Bbf[idx] = __float2bfloat16_rn(x0*wb0 + x1*wb1 + x2*wb2);
    g_Abf[idx] = __float2bfloat16_rn(x0*wa0 + x1*wa1 + x2*wa2 + b1[c]);
    g_AGG[idx] = 0;
    if (c == 0) g_cnt[i] = 0;
}

// ---------------------------------------------------------------------------
// W2 preconvert: f32 -> bf16 (one small launch).
// ---------------------------------------------------------------------------
__global__ void k_w2bf(const float* __restrict__ w2)
{
    int i = blockIdx.x * 256 + threadIdx.x;   // over float2 pairs: 8192
    if (i < HID * HID / 2) {
        float2 v = ((const float2*)w2)[i];
        ((u32*)g_w2bf)[i] = f2bf2(v.x, v.y);
    }
}

// ---------------------------------------------------------------------------
// S1: histogram of dst degrees.
// ---------------------------------------------------------------------------
__global__ void k_hist(const int* __restrict__ ei, int E)
{
    int e = blockIdx.x * 256 + threadIdx.x;
    if (e < E) atomicAdd(&g_cnt[ei[E + e]], 1);
}

// ---------------------------------------------------------------------------
// S2: single-block exclusive scan of g_cnt -> g_off.
// ---------------------------------------------------------------------------
__global__ void __launch_bounds__(1024, 1) k_scan(int n)
{
    __shared__ int wsum[32];
    __shared__ int carry;
    int tid  = threadIdx.x;
    int lane = tid & 31;
    int w    = tid >> 5;
    if (tid == 0) carry = 0;
    __syncthreads();

    for (int base = 0; base < n; base += 1024) {
        int i = base + tid;
        int v = (i < n) ? g_cnt[i] : 0;
        int xv = v;
        #pragma unroll
        for (int off = 1; off < 32; off <<= 1) {
            int y = __shfl_up_sync(0xffffffffu, xv, off);
            if (lane >= off) xv += y;
        }
        if (lane == 31) wsum[w] = xv;
        __syncthreads();
        if (w == 0) {
            int t = wsum[lane];
            #pragma unroll
            for (int off = 1; off < 32; off <<= 1) {
                int y = __shfl_up_sync(0xffffffffu, t, off);
                if (lane >= off) t += y;
            }
            wsum[lane] = t;
        }
        __syncthreads();
        int woff = (w > 0) ? wsum[w - 1] : 0;
        int incl = xv + woff;
        if (i < n) g_off[i] = carry + incl - v;
        __syncthreads();
        if (tid == 0) carry += wsum[31];
        __syncthreads();
    }
}

// ---------------------------------------------------------------------------
// S3: scatter edges into dst-sorted order.
// ---------------------------------------------------------------------------
__global__ void k_scatter(const int* __restrict__ ei, int E)
{
    int e = blockIdx.x * 256 + threadIdx.x;
    if (e < E) {
        int s = ei[e];
        int d = ei[E + e];
        int p = atomicAdd(&g_off[d], 1);
        g_ssrc[p] = s;
        g_sdst[p] = d;
    }
}

// ---------------------------------------------------------------------------
// K2: bf16 tensor-core edge kernel over dst-sorted edges.
// smem: sw2 bf16 [128][LDW]  |  sa bf16 [128][LDW] (h-tile overlays sa as bf16x2)
// ---------------------------------------------------------------------------
__global__ void __launch_bounds__(256, 2)
k_edge(int E, const float* __restrict__ b2)
{
    extern __shared__ char smraw[];
    __nv_bfloat16* sw2 = (__nv_bfloat16*)smraw;
    __nv_bfloat16* sa  = (__nv_bfloat16*)(smraw + 128 * LDW * 2);
    u32*           shu = (u32*)sa;            // h-tile overlay, LDW/2=68 u32/row
    __shared__ int sdst[TE];

    int tid = threadIdx.x;
    int tile0 = blockIdx.x * TE;

    // load w2 (bf16) -> smem [k][LDW]; 2048 uint4, 8 per thread
    {
        const uint4* gv = (const uint4*)g_w2bf;
        #pragma unroll
        for (int it = 0; it < 8; it++) {
            int idx = tid + it * 256;        // uint4 id; 16 per k-row
            int k    = idx >> 4;
            int col8 = (idx & 15) * 8;
            *(uint4*)(sw2 + k * LDW + col8) = gv[idx];
        }
    }

    // gather relu(A[dst]+B[src]) in packed bf16, 2 threads/edge
    {
        int e  = tid >> 1;
        int hf = tid & 1;
        int eg = tile0 + e;
        if (eg < E) {
            int s = g_ssrc[eg];
            int d = g_sdst[eg];
            if (hf == 0) sdst[e] = d;
            const uint4* Av = (const uint4*)(g_Abf + (size_t)d * HID) + hf*8;
            const uint4* Bv = (const uint4*)(g_Bbf + (size_t)s * HID) + hf*8;
            #pragma unroll
            for (int j = 0; j < 8; j++) {
                uint4 a = Av[j];
                uint4 b = Bv[j];
                uint4 r;
                r.x = hadd_relu2(a.x, b.x);
                r.y = hadd_relu2(a.y, b.y);
                r.z = hadd_relu2(a.z, b.z);
                r.w = hadd_relu2(a.w, b.w);
                *(uint4*)(sa + e * LDW + hf*64 + j*8) = r;
            }
        } else {
            if (hf == 0) sdst[e] = -1;
            uint4 z = make_uint4(0u, 0u, 0u, 0u);
            #pragma unroll
            for (int j = 0; j < 8; j++)
                *(uint4*)(sa + e * LDW + hf*64 + j*8) = z;
        }
    }
    __syncthreads();

    int lane = tid & 31;
    int wid  = tid >> 5;
    int e0   = (wid >> 1) * 32;
    int n0w  = (wid & 1) * 64;

    float acc[2][8][4];
    #pragma unroll
    for (int m = 0; m < 2; m++) {
        #pragma unroll
        for (int t = 0; t < 8; t++) {
            #pragma unroll
            for (int i = 0; i < 4; i++) acc[m][t][i] = 0.f;
        }
    }

    int rsel = lane & 15;
    int csel = (lane >> 4) << 3;

    #pragma unroll
    for (int k0 = 0; k0 < HID; k0 += 16) {
        u32 A0[4];
        u32 A1[4];
        ldsm_x4(A0, smaddr(sa + (e0 +      rsel) * LDW + k0 + csel));
        ldsm_x4(A1, smaddr(sa + (e0 + 16 + rsel) * LDW + k0 + csel));
        #pragma unroll
        for (int t = 0; t < 4; t++) {
            u32 Bf[4];
            ldsm_x4_t(Bf, smaddr(sw2 + (k0 + rsel) * LDW + n0w + t*16 + csel));
            mma16816(acc[0][2*t+0], A0, Bf[0], Bf[1]);
            mma16816(acc[0][2*t+1], A0, Bf[2], Bf[3]);
            mma16816(acc[1][2*t+0], A1, Bf[0], Bf[1]);
            mma16816(acc[1][2*t+1], A1, Bf[2], Bf[3]);
        }
    }

    __syncthreads();   // all warps done reading sa before overlay

    // store h fragments as bf16x2 into shu [edge][64 pairs]
    {
        int r0 = lane >> 2;
        int cq = (lane & 3) * 2;
        #pragma unroll
        for (int m = 0; m < 2; m++) {
            int rbase = e0 + m*16 + r0;
            #pragma unroll
            for (int t = 0; t < 8; t++) {
                int cp = (n0w + t*8 + cq) >> 1;    // u32 pair index
                shu[rbase       * (LDW/2) + cp] = f2bf2(acc[m][t][0], acc[m][t][1]);
                shu[(rbase + 8) * (LDW/2) + cp] = f2bf2(acc[m][t][2], acc[m][t][3]);
            }
        }
    }
    __syncthreads();

    // segmented max over dst-groups (packed bf16x2 channel pairs).
    // thread: pair p = tid&63 (channels 2p,2p+1), edges [(tid>>6)*32, +32).
    {
        int p  = tid & 63;
        int eb = (tid >> 6) * 32;
        float2 bb = *(const float2*)(b2 + 2*p);
        int prev = sdst[eb];
        u32 mx = shu[eb * (LDW/2) + p];
        #pragma unroll 4
        for (int j = 1; j < 32; j++) {
            int d2 = sdst[eb + j];
            u32 v  = shu[(eb + j) * (LDW/2) + p];
            if (d2 != prev) {
                if (prev >= 0) {
                    float2 f = __bfloat1622float2(*reinterpret_cast<__nv_bfloat162*>(&mx));
                    atomicMax(g_AGG + (size_t)prev * HID + 2*p,
                              __float_as_int(fmaxf(f.x + bb.x, 0.f)));
                    atomicMax(g_AGG + (size_t)prev * HID + 2*p + 1,
                              __float_as_int(fmaxf(f.y + bb.y, 0.f)));
                }
                prev = d2;
                mx = v;
            } else {
                mx = hmax2u(mx, v);
            }
        }
        if (prev >= 0) {
            float2 f = __bfloat1622float2(*reinterpret_cast<__nv_bfloat162*>(&mx));
            atomicMax(g_AGG + (size_t)prev * HID + 2*p,
                      __float_as_int(fmaxf(f.x + bb.x, 0.f)));
            atomicMax(g_AGG + (size_t)prev * HID + 2*p + 1,
                      __float_as_int(fmaxf(f.y + bb.y, 0.f)));
        }
    }
}

// ---------------------------------------------------------------------------
// K3: per-node tail (packed f32x2 GEMMs). Unchanged (proven).
// ---------------------------------------------------------------------------
__global__ void __launch_bounds__(256, 1)
k_node_post(const float* __restrict__ pos,
            const float* __restrict__ w3, const float* __restrict__ b3,
            const float* __restrict__ w4, const float* __restrict__ b4,
            const float* __restrict__ w5, const float* __restrict__ b5,
            float* __restrict__ out, int n)
{
    extern __shared__ char smraw[];
    float* sw3 = (float*)smraw;
    float* sw4 = sw3 + 16384;
    float* sx  = sw3 + 32768;

    int tid = threadIdx.x;
    int n0 = blockIdx.x * TN;

    {
        const float4* g3 = (const float4*)w3;
        const float4* g4 = (const float4*)w4;
        float4* s3 = (float4*)sw3;
        float4* s4 = (float4*)sw4;
        #pragma unroll
        for (int i = 0; i < 16; i++) {
            s3[tid + i*256] = g3[tid + i*256];
            s4[tid + i*256] = g4[tid + i*256];
        }
    }

    {
        int e = tid & 63;
        int q = tid >> 6;
        int node = n0 + e;
        if (node < n) {
            const float4* Gv = (const float4*)((const float*)g_AGG + (size_t)node * HID);
            #pragma unroll
            for (int j = 0; j < 8; j++) {
                float4 a = Gv[q*8 + j];
                int k = q*32 + j*4;
                sx[(k+0)*TN + e] = a.x;
                sx[(k+1)*TN + e] = a.y;
                sx[(k+2)*TN + e] = a.z;
                sx[(k+3)*TN + e] = a.w;
            }
        } else {
            #pragma unroll
            for (int j = 0; j < 8; j++) {
                int k = q*32 + j*4;
                sx[(k+0)*TN + e] = 0.f;
                sx[(k+1)*TN + e] = 0.f;
                sx[(k+2)*TN + e] = 0.f;
                sx[(k+3)*TN + e] = 0.f;
            }
        }
    }
    __syncthreads();

    int tx = tid & 15;
    int ty = tid >> 4;

    ull acc[4][4];
    #pragma unroll
    for (int j = 0; j < 4; j++) {
        #pragma unroll
        for (int p = 0; p < 4; p++) acc[j][p] = 0ULL;
    }

    // GEMM1: enc = agg @ w3
    {
        const float* rp  = sx + ty*4;
        const float* wp0 = sw3 + tx*8;
        #pragma unroll 4
        for (int k = 0; k < HID; k++) {
            float4 r = *(const float4*)(rp + k*TN);
            ulonglong2 w01 = *(const ulonglong2*)(wp0 + k*HID);
            ulonglong2 w23 = *(const ulonglong2*)(wp0 + k*HID + 4);
            ull wpk[4] = {w01.x, w01.y, w23.x, w23.y};
            float rv[4] = {r.x, r.y, r.z, r.w};
            #pragma unroll
            for (int j = 0; j < 4; j++) {
                ull rr = pack2(rv[j], rv[j]);
                #pragma unroll
                for (int p = 0; p < 4; p++) fma2(acc[j][p], rr, wpk[p]);
            }
        }
    }
    float b3r[8];
    #pragma unroll
    for (int c = 0; c < 8; c++) b3r[c] = b3[tx*8 + c];

    __syncthreads();
    #pragma unroll
    for (int p = 0; p < 4; p++) {
        #pragma unroll
        for (int j = 0; j < 4; j++) {
            float2 v = unpack2(acc[j][p]);
            sx[(tx*8 + 2*p + 0)*TN + ty*4 + j] = v.x + b3r[2*p+0];
            sx[(tx*8 + 2*p + 1)*TN + ty*4 + j] = v.y + b3r[2*p+1];
        }
    }
    __syncthreads();

    // GEMM2: pre-act of (enc @ w4 + b4)
    #pragma unroll
    for (int j = 0; j < 4; j++) {
        #pragma unroll
        for (int p = 0; p < 4; p++) acc[j][p] = 0ULL;
    }
    {
        const float* rp  = sx + ty*4;
        const float* wp0 = sw4 + tx*8;
        #pragma unroll 4
        for (int k = 0; k < HID; k++) {
            float4 r = *(const float4*)(rp + k*TN);
            ulonglong2 w01 = *(const ulonglong2*)(wp0 + k*HID);
            ulonglong2 w23 = *(const ulonglong2*)(wp0 + k*HID + 4);
            ull wpk[4] = {w01.x, w01.y, w23.x, w23.y};
            float rv[4] = {r.x, r.y, r.z, r.w};
            #pragma unroll
            for (int j = 0; j < 4; j++) {
                ull rr = pack2(rv[j], rv[j]);
                #pragma unroll
                for (int p = 0; p < 4; p++) fma2(acc[j][p], rr, wpk[p]);
            }
        }
    }
    float b4r[8];
    #pragma unroll
    for (int c = 0; c < 8; c++) b4r[c] = b4[tx*8 + c];

    float ac[4][8];
    #pragma unroll
    for (int j = 0; j < 4; j++) {
        #pragma unroll
        for (int p = 0; p < 4; p++) {
            float2 v = unpack2(acc[j][p]);
            ac[j][2*p+0] = v.x;
            ac[j][2*p+1] = v.y;
        }
    }

    float pd[4][3];
    #pragma unroll
    for (int j = 0; j < 4; j++) {
        pd[j][0] = 0.f; pd[j][1] = 0.f; pd[j][2] = 0.f;
    }
    #pragma unroll
    for (int c = 0; c < 8; c++) {
        int cg = tx*8 + c;
        float w50 = w5[cg*3 + 0];
        float w51 = w5[cg*3 + 1];
        float w52 = w5[cg*3 + 2];
        #pragma unroll
        for (int j = 0; j < 4; j++) {
            float t = fmaxf(ac[j][c] + b4r[c], 0.f);
            pd[j][0] = fmaf(t, w50, pd[j][0]);
            pd[j][1] = fmaf(t, w51, pd[j][1]);
            pd[j][2] = fmaf(t, w52, pd[j][2]);
        }
    }
    #pragma unroll
    for (int o = 8; o >= 1; o >>= 1) {
        #pragma unroll
        for (int j = 0; j < 4; j++) {
            #pragma unroll
            for (int d = 0; d < 3; d++)
                pd[j][d] += __shfl_xor_sync(0xffffffffu, pd[j][d], o);
        }
    }

    if (tx == 0) {
        float b50 = b5[0];
        float b51 = b5[1];
        float b52 = b5[2];
        #pragma unroll
        for (int j = 0; j < 4; j++) {
            int nd = n0 + ty*4 + j;
            if (nd < n) {
                out[nd*3 + 0] = pos[nd*3 + 0] + 0.1f * tanhf(pd[j][0] + b50);
                out[nd*3 + 1] = pos[nd*3 + 1] + 0.1f * tanhf(pd[j][1] + b51);
                out[nd*3 + 2] = pos[nd*3 + 2] + 0.1f * tanhf(pd[j][2] + b52);
            }
        }
    }
}

// ---------------------------------------------------------------------------
extern "C" void kernel_launch(void* const* d_in, const int* in_sizes, int n_in,
                              void* d_out, int out_size)
{
    const float* x   = (const float*)d_in[0];
    const float* pos = (const float*)d_in[1];
    const int*   ei  = (const int*)d_in[2];   // int32
    const float* w1 = (const float*)d_in[3];
    const float* b1 = (const float*)d_in[4];
    const float* w2 = (const float*)d_in[5];
    const float* b2 = (const float*)d_in[6];
    const float* w3 = (const float*)d_in[7];
    const float* b3 = (const float*)d_in[8];
    const float* w4 = (const float*)d_in[9];
    const float* b4 = (const float*)d_in[10];
    const float* w5 = (const float*)d_in[11];
    const float* b5 = (const float*)d_in[12];
    float* out = (float*)d_out;

    int n = in_sizes[0] / 3;      // 100000
    int E = in_sizes[2] / 2;      // 1600000

    (void)n_in;
    (void)out_size;

    const int EDGE_SMEM = 2 * 128 * LDW * 2;                             // 69632
    const int NODE_SMEM = (2*HID*HID + HID*TN) * (int)sizeof(float);     // 163840
    cudaFuncSetAttribute(k_edge, cudaFuncAttributeMaxDynamicSharedMemorySize, EDGE_SMEM);
    cudaFuncSetAttribute(k_node_post, cudaFuncAttributeMaxDynamicSharedMemorySize, NODE_SMEM);

    int gpre = (n * HID + 255) / 256;
    k_node_pre<<<gpre, 256>>>(x, w1, b1, n);
    k_w2bf<<<32, 256>>>(w2);

    int ge = (E + 255) / 256;
    k_hist<<<ge, 256>>>(ei, E);
    k_scan<<<1, 1024>>>(n);
    k_scatter<<<ge, 256>>>(ei, E);

    int gedge = (E + TE - 1) / TE;
    k_edge<<<gedge, 256, EDGE_SMEM>>>(E, b2);

    int gnode = (n + TN - 1) / TN;
    k_node_post<<<gnode, 256, NODE_SMEM>>>(pos, w3, b3, w4, b4, w5, b5, out, n);
}

// round 11
// speedup vs baseline: 9.6982x; 1.6120x over previous
#include <cuda_runtime.h>
#include <cuda_bf16.h>
#include <cstdint>
#include <math.h>

#define HID   128
#define NMAX  100000
#define EMAX  1600000
#define TE    128    // edges per tile in edge kernel
#define LDW   136    // bf16 row stride in smem (272B, 16B-aligned rows)

typedef unsigned long long ull;
typedef unsigned int u32;

// Scratch (static device globals — no runtime allocation).
__device__ __nv_bfloat16 g_Abf[(size_t)NMAX * HID];  // per-node dst term (bf16)
__device__ __nv_bfloat16 g_Bbf[(size_t)NMAX * HID];  // per-node src term (bf16)
__device__ __nv_bfloat16 g_w2bf[HID * HID];          // weights in bf16 [k][c]
__device__ __nv_bfloat16 g_w3bf[HID * HID];
__device__ __nv_bfloat16 g_w4bf[HID * HID];
__device__ int   g_AGG[(size_t)NMAX * HID]; // relu(segment_max) as float bits
__device__ int   g_cnt[NMAX];               // per-dst degree
__device__ int   g_off[NMAX];               // exclusive offsets (consumed as cursors)
__device__ int   g_bsum[128];               // per-scan-block totals
__device__ int   g_ssrc[EMAX];              // src sorted by dst
__device__ int   g_sdst[EMAX];              // dst sorted (non-decreasing)

// ---- bf16 helpers ----------------------------------------------------------
__device__ __forceinline__ u32 smaddr(const void* p) {
    return (u32)__cvta_generic_to_shared(p);
}
__device__ __forceinline__ void ldsm_x4(u32* r, u32 a) {
    asm volatile("ldmatrix.sync.aligned.m8n8.x4.shared.b16 {%0,%1,%2,%3}, [%4];"
        : "=r"(r[0]), "=r"(r[1]), "=r"(r[2]), "=r"(r[3]) : "r"(a));
}
__device__ __forceinline__ void ldsm_x4_t(u32* r, u32 a) {
    asm volatile("ldmatrix.sync.aligned.m8n8.x4.trans.shared.b16 {%0,%1,%2,%3}, [%4];"
        : "=r"(r[0]), "=r"(r[1]), "=r"(r[2]), "=r"(r[3]) : "r"(a));
}
__device__ __forceinline__ void mma16816(float* c, const u32* a, u32 b0, u32 b1) {
    asm volatile("mma.sync.aligned.m16n8k16.row.col.f32.bf16.bf16.f32 "
        "{%0,%1,%2,%3}, {%4,%5,%6,%7}, {%8,%9}, {%0,%1,%2,%3};"
        : "+f"(c[0]), "+f"(c[1]), "+f"(c[2]), "+f"(c[3])
        : "r"(a[0]), "r"(a[1]), "r"(a[2]), "r"(a[3]), "r"(b0), "r"(b1));
}
__device__ __forceinline__ u32 f2bf2(float lo, float hi) {
    __nv_bfloat162 h2 = __floats2bfloat162_rn(lo, hi);
    return *reinterpret_cast<u32*>(&h2);
}
__device__ __forceinline__ u32 hadd_relu2(u32 ua, u32 ub) {
    __nv_bfloat162 a = *reinterpret_cast<__nv_bfloat162*>(&ua);
    __nv_bfloat162 b = *reinterpret_cast<__nv_bfloat162*>(&ub);
    u32 uz = 0u;
    __nv_bfloat162 z = *reinterpret_cast<__nv_bfloat162*>(&uz);
    __nv_bfloat162 r = __hmax2(__hadd2(a, b), z);
    return *reinterpret_cast<u32*>(&r);
}
__device__ __forceinline__ u32 hmax2u(u32 ua, u32 ub) {
    __nv_bfloat162 a = *reinterpret_cast<__nv_bfloat162*>(&ua);
    __nv_bfloat162 b = *reinterpret_cast<__nv_bfloat162*>(&ub);
    __nv_bfloat162 r = __hmax2(a, b);
    return *reinterpret_cast<u32*>(&r);
}

// ---------------------------------------------------------------------------
// K1: per-node layer-1 terms (bf16) + zero AGG + zero degree counters.
// ---------------------------------------------------------------------------
__global__ void k_node_pre(const float* __restrict__ x,
                           const float* __restrict__ w1,
                           const float* __restrict__ b1, int n)
{
    int idx = blockIdx.x * 256 + threadIdx.x;
    if (idx >= n * HID) return;
    int i = idx >> 7;
    int c = idx & 127;
    float x0 = x[i*3+0], x1 = x[i*3+1], x2 = x[i*3+2];
    float wb0 = w1[3*HID+c], wb1 = w1[4*HID+c], wb2 = w1[5*HID+c];
    float wa0 = w1[0*HID+c] - wb0;
    float wa1 = w1[1*HID+c] - wb1;
    float wa2 = w1[2*HID+c] - wb2;
    g_Bbf[idx] = __float2bfloat16_rn(x0*wb0 + x1*wb1 + x2*wb2);
    g_Abf[idx] = __float2bfloat16_rn(x0*wa0 + x1*wa1 + x2*wa2 + b1[c]);
    g_AGG[idx] = 0;
    if (c == 0) g_cnt[i] = 0;
}

// ---------------------------------------------------------------------------
// Weight preconvert: w2, w3, w4 f32 -> bf16 (one small launch).
// ---------------------------------------------------------------------------
__global__ void k_wconv(const float* __restrict__ w2,
                        const float* __restrict__ w3,
                        const float* __restrict__ w4)
{
    int i = blockIdx.x * 256 + threadIdx.x;   // 3 * 8192 pairs
    const int P = HID * HID / 2;              // 8192
    if (i < P) {
        float2 v = ((const float2*)w2)[i];
        ((u32*)g_w2bf)[i] = f2bf2(v.x, v.y);
    } else if (i < 2*P) {
        float2 v = ((const float2*)w3)[i - P];
        ((u32*)g_w3bf)[i - P] = f2bf2(v.x, v.y);
    } else if (i < 3*P) {
        float2 v = ((const float2*)w4)[i - 2*P];
        ((u32*)g_w4bf)[i - 2*P] = f2bf2(v.x, v.y);
    }
}

// ---------------------------------------------------------------------------
// S1: histogram of dst degrees.
// ---------------------------------------------------------------------------
__global__ void k_hist(const int* __restrict__ ei, int E)
{
    int e = blockIdx.x * 256 + threadIdx.x;
    if (e < E) atomicAdd(&g_cnt[ei[E + e]], 1);
}

// ---------------------------------------------------------------------------
// S2a: per-block exclusive scan (1024-chunks in parallel) + block totals.
// ---------------------------------------------------------------------------
__global__ void __launch_bounds__(1024, 1) k_scan1(int n)
{
    __shared__ int wsum[32];
    int tid  = threadIdx.x;
    int lane = tid & 31;
    int w    = tid >> 5;
    int i = blockIdx.x * 1024 + tid;
    int v = (i < n) ? g_cnt[i] : 0;
    int xv = v;
    #pragma unroll
    for (int off = 1; off < 32; off <<= 1) {
        int y = __shfl_up_sync(0xffffffffu, xv, off);
        if (lane >= off) xv += y;
    }
    if (lane == 31) wsum[w] = xv;
    __syncthreads();
    if (w == 0) {
        int t = wsum[lane];
        #pragma unroll
        for (int off = 1; off < 32; off <<= 1) {
            int y = __shfl_up_sync(0xffffffffu, t, off);
            if (lane >= off) t += y;
        }
        wsum[lane] = t;
    }
    __syncthreads();
    int woff = (w > 0) ? wsum[w - 1] : 0;
    if (i < n) g_off[i] = woff + xv - v;       // block-local exclusive
    if (tid == 0) g_bsum[blockIdx.x] = wsum[31];
}

// ---------------------------------------------------------------------------
// S2b: one-warp exclusive scan of block totals (nb <= 128).
// ---------------------------------------------------------------------------
__global__ void k_scan2(int nb)
{
    int lane = threadIdx.x;
    int carry = 0;
    for (int base = 0; base < nb; base += 32) {
        int i = base + lane;
        int v = (i < nb) ? g_bsum[i] : 0;
        int xv = v;
        #pragma unroll
        for (int off = 1; off < 32; off <<= 1) {
            int y = __shfl_up_sync(0xffffffffu, xv, off);
            if (lane >= off) xv += y;
        }
        if (i < nb) g_bsum[i] = carry + xv - v;
        carry += __shfl_sync(0xffffffffu, xv, 31);
    }
}

// ---------------------------------------------------------------------------
// S2c: add scanned block offsets back.
// ---------------------------------------------------------------------------
__global__ void k_scan3(int n)
{
    int i = blockIdx.x * 256 + threadIdx.x;
    if (i < n) g_off[i] += g_bsum[i >> 10];
}

// ---------------------------------------------------------------------------
// S3: scatter edges into dst-sorted order.
// ---------------------------------------------------------------------------
__global__ void k_scatter(const int* __restrict__ ei, int E)
{
    int e = blockIdx.x * 256 + threadIdx.x;
    if (e < E) {
        int s = ei[e];
        int d = ei[E + e];
        int p = atomicAdd(&g_off[d], 1);
        g_ssrc[p] = s;
        g_sdst[p] = d;
    }
}

// ---------------------------------------------------------------------------
// K2: bf16 tensor-core edge kernel over dst-sorted edges (unchanged, proven).
// ---------------------------------------------------------------------------
__global__ void __launch_bounds__(256, 2)
k_edge(int E, const float* __restrict__ b2)
{
    extern __shared__ char smraw[];
    __nv_bfloat16* sw2 = (__nv_bfloat16*)smraw;
    __nv_bfloat16* sa  = (__nv_bfloat16*)(smraw + 128 * LDW * 2);
    u32*           shu = (u32*)sa;            // h-tile overlay
    __shared__ int sdst[TE];

    int tid = threadIdx.x;
    int tile0 = blockIdx.x * TE;

    {
        const uint4* gv = (const uint4*)g_w2bf;
        #pragma unroll
        for (int it = 0; it < 8; it++) {
            int idx = tid + it * 256;
            int k    = idx >> 4;
            int col8 = (idx & 15) * 8;
            *(uint4*)(sw2 + k * LDW + col8) = gv[idx];
        }
    }

    {
        int e  = tid >> 1;
        int hf = tid & 1;
        int eg = tile0 + e;
        if (eg < E) {
            int s = g_ssrc[eg];
            int d = g_sdst[eg];
            if (hf == 0) sdst[e] = d;
            const uint4* Av = (const uint4*)(g_Abf + (size_t)d * HID) + hf*8;
            const uint4* Bv = (const uint4*)(g_Bbf + (size_t)s * HID) + hf*8;
            #pragma unroll
            for (int j = 0; j < 8; j++) {
                uint4 a = Av[j];
                uint4 b = Bv[j];
                uint4 r;
                r.x = hadd_relu2(a.x, b.x);
                r.y = hadd_relu2(a.y, b.y);
                r.z = hadd_relu2(a.z, b.z);
                r.w = hadd_relu2(a.w, b.w);
                *(uint4*)(sa + e * LDW + hf*64 + j*8) = r;
            }
        } else {
            if (hf == 0) sdst[e] = -1;
            uint4 z = make_uint4(0u, 0u, 0u, 0u);
            #pragma unroll
            for (int j = 0; j < 8; j++)
                *(uint4*)(sa + e * LDW + hf*64 + j*8) = z;
        }
    }
    __syncthreads();

    int lane = tid & 31;
    int wid  = tid >> 5;
    int e0   = (wid >> 1) * 32;
    int n0w  = (wid & 1) * 64;

    float acc[2][8][4];
    #pragma unroll
    for (int m = 0; m < 2; m++) {
        #pragma unroll
        for (int t = 0; t < 8; t++) {
            #pragma unroll
            for (int i = 0; i < 4; i++) acc[m][t][i] = 0.f;
        }
    }

    int rsel = lane & 15;
    int csel = (lane >> 4) << 3;

    #pragma unroll
    for (int k0 = 0; k0 < HID; k0 += 16) {
        u32 A0[4];
        u32 A1[4];
        ldsm_x4(A0, smaddr(sa + (e0 +      rsel) * LDW + k0 + csel));
        ldsm_x4(A1, smaddr(sa + (e0 + 16 + rsel) * LDW + k0 + csel));
        #pragma unroll
        for (int t = 0; t < 4; t++) {
            u32 Bf[4];
            ldsm_x4_t(Bf, smaddr(sw2 + (k0 + rsel) * LDW + n0w + t*16 + csel));
            mma16816(acc[0][2*t+0], A0, Bf[0], Bf[1]);
            mma16816(acc[0][2*t+1], A0, Bf[2], Bf[3]);
            mma16816(acc[1][2*t+0], A1, Bf[0], Bf[1]);
            mma16816(acc[1][2*t+1], A1, Bf[2], Bf[3]);
        }
    }

    __syncthreads();

    {
        int r0 = lane >> 2;
        int cq = (lane & 3) * 2;
        #pragma unroll
        for (int m = 0; m < 2; m++) {
            int rbase = e0 + m*16 + r0;
            #pragma unroll
            for (int t = 0; t < 8; t++) {
                int cp = (n0w + t*8 + cq) >> 1;
                shu[rbase       * (LDW/2) + cp] = f2bf2(acc[m][t][0], acc[m][t][1]);
                shu[(rbase + 8) * (LDW/2) + cp] = f2bf2(acc[m][t][2], acc[m][t][3]);
            }
        }
    }
    __syncthreads();

    {
        int p  = tid & 63;
        int eb = (tid >> 6) * 32;
        float2 bb = *(const float2*)(b2 + 2*p);
        int prev = sdst[eb];
        u32 mx = shu[eb * (LDW/2) + p];
        #pragma unroll 4
        for (int j = 1; j < 32; j++) {
            int d2 = sdst[eb + j];
            u32 v  = shu[(eb + j) * (LDW/2) + p];
            if (d2 != prev) {
                if (prev >= 0) {
                    float2 f = __bfloat1622float2(*reinterpret_cast<__nv_bfloat162*>(&mx));
                    atomicMax(g_AGG + (size_t)prev * HID + 2*p,
                              __float_as_int(fmaxf(f.x + bb.x, 0.f)));
                    atomicMax(g_AGG + (size_t)prev * HID + 2*p + 1,
                              __float_as_int(fmaxf(f.y + bb.y, 0.f)));
                }
                prev = d2;
                mx = v;
            } else {
                mx = hmax2u(mx, v);
            }
        }
        if (prev >= 0) {
            float2 f = __bfloat1622float2(*reinterpret_cast<__nv_bfloat162*>(&mx));
            atomicMax(g_AGG + (size_t)prev * HID + 2*p,
                      __float_as_int(fmaxf(f.x + bb.x, 0.f)));
            atomicMax(g_AGG + (size_t)prev * HID + 2*p + 1,
                      __float_as_int(fmaxf(f.y + bb.y, 0.f)));
        }
    }
}

// ---------------------------------------------------------------------------
// K3: bf16 tensor-core node tail. 128-node tiles.
//  enc = agg @ w3 + b3 ; t = relu(enc @ w4 + b4) ; dec = t @ w5 + b5
//  out = pos + 0.1*tanh(dec)
// smem: sw3 [128][LDW] | sw4 [128][LDW] | sa [128][LDW] (agg -> enc -> t)
// ---------------------------------------------------------------------------
__global__ void __launch_bounds__(256, 2)
k_node_post(const float* __restrict__ pos,
            const float* __restrict__ b3, const float* __restrict__ b4,
            const float* __restrict__ w5, const float* __restrict__ b5,
            float* __restrict__ out, int n)
{
    extern __shared__ char smraw[];
    __nv_bfloat16* sw3 = (__nv_bfloat16*)smraw;
    __nv_bfloat16* sw4 = sw3 + 128 * LDW;
    __nv_bfloat16* sa  = sw4 + 128 * LDW;
    u32*           sau = (u32*)sa;
    __shared__ float sw5[HID * 3];

    int tid = threadIdx.x;
    int n0 = blockIdx.x * 128;

    // load w3, w4 bf16 -> smem
    {
        const uint4* g3 = (const uint4*)g_w3bf;
        const uint4* g4 = (const uint4*)g_w4bf;
        #pragma unroll
        for (int it = 0; it < 8; it++) {
            int idx = tid + it * 256;
            int k    = idx >> 4;
            int col8 = (idx & 15) * 8;
            *(uint4*)(sw3 + k * LDW + col8) = g3[idx];
            *(uint4*)(sw4 + k * LDW + col8) = g4[idx];
        }
        if (tid < 192) ((float2*)sw5)[tid] = ((const float2*)w5)[tid];
    }

    // load agg (f32 bits in g_AGG) -> bf16 sa; 2 threads/row
    {
        int r  = tid >> 1;
        int hf = tid & 1;
        int node = n0 + r;
        if (node < n) {
            const float4* Gv = (const float4*)((const float*)g_AGG + (size_t)node * HID) + hf*16;
            #pragma unroll
            for (int j = 0; j < 8; j++) {
                float4 a = Gv[2*j];
                float4 b = Gv[2*j + 1];
                uint4 rr;
                rr.x = f2bf2(a.x, a.y);
                rr.y = f2bf2(a.z, a.w);
                rr.z = f2bf2(b.x, b.y);
                rr.w = f2bf2(b.z, b.w);
                *(uint4*)(sa + r * LDW + hf*64 + j*8) = rr;
            }
        } else {
            uint4 z = make_uint4(0u, 0u, 0u, 0u);
            #pragma unroll
            for (int j = 0; j < 8; j++)
                *(uint4*)(sa + r * LDW + hf*64 + j*8) = z;
        }
    }
    __syncthreads();

    int lane = tid & 31;
    int wid  = tid >> 5;
    int e0   = (wid >> 1) * 32;
    int n0w  = (wid & 1) * 64;
    int rsel = lane & 15;
    int csel = (lane >> 4) << 3;
    int r0   = lane >> 2;
    int cq   = (lane & 3) * 2;

    float acc[2][8][4];

    // ---- GEMM1: enc = agg @ w3 ----
    #pragma unroll
    for (int m = 0; m < 2; m++) {
        #pragma unroll
        for (int t = 0; t < 8; t++) {
            #pragma unroll
            for (int i = 0; i < 4; i++) acc[m][t][i] = 0.f;
        }
    }
    #pragma unroll
    for (int k0 = 0; k0 < HID; k0 += 16) {
        u32 A0[4];
        u32 A1[4];
        ldsm_x4(A0, smaddr(sa + (e0 +      rsel) * LDW + k0 + csel));
        ldsm_x4(A1, smaddr(sa + (e0 + 16 + rsel) * LDW + k0 + csel));
        #pragma unroll
        for (int t = 0; t < 4; t++) {
            u32 Bf[4];
            ldsm_x4_t(Bf, smaddr(sw3 + (k0 + rsel) * LDW + n0w + t*16 + csel));
            mma16816(acc[0][2*t+0], A0, Bf[0], Bf[1]);
            mma16816(acc[0][2*t+1], A0, Bf[2], Bf[3]);
            mma16816(acc[1][2*t+0], A1, Bf[0], Bf[1]);
            mma16816(acc[1][2*t+1], A1, Bf[2], Bf[3]);
        }
    }
    __syncthreads();   // all warps done reading sa

    // store enc = acc + b3 as bf16 into sa
    #pragma unroll
    for (int m = 0; m < 2; m++) {
        int rbase = e0 + m*16 + r0;
        #pragma unroll
        for (int t = 0; t < 8; t++) {
            int c = n0w + t*8 + cq;
            float bb0 = b3[c];
            float bb1 = b3[c+1];
            sau[rbase       * (LDW/2) + (c >> 1)] = f2bf2(acc[m][t][0] + bb0, acc[m][t][1] + bb1);
            sau[(rbase + 8) * (LDW/2) + (c >> 1)] = f2bf2(acc[m][t][2] + bb0, acc[m][t][3] + bb1);
        }
    }
    __syncthreads();

    // ---- GEMM2: t = relu(enc @ w4 + b4) ----
    #pragma unroll
    for (int m = 0; m < 2; m++) {
        #pragma unroll
        for (int t = 0; t < 8; t++) {
            #pragma unroll
            for (int i = 0; i < 4; i++) acc[m][t][i] = 0.f;
        }
    }
    #pragma unroll
    for (int k0 = 0; k0 < HID; k0 += 16) {
        u32 A0[4];
        u32 A1[4];
        ldsm_x4(A0, smaddr(sa + (e0 +      rsel) * LDW + k0 + csel));
        ldsm_x4(A1, smaddr(sa + (e0 + 16 + rsel) * LDW + k0 + csel));
        #pragma unroll
        for (int t = 0; t < 4; t++) {
            u32 Bf[4];
            ldsm_x4_t(Bf, smaddr(sw4 + (k0 + rsel) * LDW + n0w + t*16 + csel));
            mma16816(acc[0][2*t+0], A0, Bf[0], Bf[1]);
            mma16816(acc[0][2*t+1], A0, Bf[2], Bf[3]);
            mma16816(acc[1][2*t+0], A1, Bf[0], Bf[1]);
            mma16816(acc[1][2*t+1], A1, Bf[2], Bf[3]);
        }
    }
    __syncthreads();

    // store t = relu(acc + b4) as bf16 into sa
    #pragma unroll
    for (int m = 0; m < 2; m++) {
        int rbase = e0 + m*16 + r0;
        #pragma unroll
        for (int t = 0; t < 8; t++) {
            int c = n0w + t*8 + cq;
            float bb0 = b4[c];
            float bb1 = b4[c+1];
            sau[rbase       * (LDW/2) + (c >> 1)] =
                f2bf2(fmaxf(acc[m][t][0] + bb0, 0.f), fmaxf(acc[m][t][1] + bb1, 0.f));
            sau[(rbase + 8) * (LDW/2) + (c >> 1)] =
                f2bf2(fmaxf(acc[m][t][2] + bb0, 0.f), fmaxf(acc[m][t][3] + bb1, 0.f));
        }
    }
    __syncthreads();

    // ---- dec = t @ w5 (128->3); out = pos + 0.1*tanh(dec + b5) ----
    {
        int r  = tid >> 1;          // node row 0..127
        int hf = tid & 1;           // channel half
        float pd0 = 0.f, pd1 = 0.f, pd2 = 0.f;
        const u32* rowp = sau + r * (LDW/2) + hf*32;
        #pragma unroll 8
        for (int j = 0; j < 32; j++) {
            u32 uv = rowp[j];
            float2 f = __bfloat1622float2(*reinterpret_cast<__nv_bfloat162*>(&uv));
            int c = hf*64 + 2*j;
            pd0 = fmaf(f.x, sw5[c*3+0], pd0);
            pd1 = fmaf(f.x, sw5[c*3+1], pd1);
            pd2 = fmaf(f.x, sw5[c*3+2], pd2);
            pd0 = fmaf(f.y, sw5[c*3+3], pd0);
            pd1 = fmaf(f.y, sw5[c*3+4], pd1);
            pd2 = fmaf(f.y, sw5[c*3+5], pd2);
        }
        pd0 += __shfl_xor_sync(0xffffffffu, pd0, 1);
        pd1 += __shfl_xor_sync(0xffffffffu, pd1, 1);
        pd2 += __shfl_xor_sync(0xffffffffu, pd2, 1);
        int node = n0 + r;
        if (hf == 0 && node < n) {
            out[node*3 + 0] = pos[node*3 + 0] + 0.1f * tanhf(pd0 + b5[0]);
            out[node*3 + 1] = pos[node*3 + 1] + 0.1f * tanhf(pd1 + b5[1]);
            out[node*3 + 2] = pos[node*3 + 2] + 0.1f * tanhf(pd2 + b5[2]);
        }
    }
}

// ---------------------------------------------------------------------------
extern "C" void kernel_launch(void* const* d_in, const int* in_sizes, int n_in,
                              void* d_out, int out_size)
{
    const float* x   = (const float*)d_in[0];
    const float* pos = (const float*)d_in[1];
    const int*   ei  = (const int*)d_in[2];   // int32
    const float* w1 = (const float*)d_in[3];
    const float* b1 = (const float*)d_in[4];
    const float* w2 = (const float*)d_in[5];
    const float* b2 = (const float*)d_in[6];
    const float* w3 = (const float*)d_in[7];
    const float* b3 = (const float*)d_in[8];
    const float* w4 = (const float*)d_in[9];
    const float* b4 = (const float*)d_in[10];
    const float* w5 = (const float*)d_in[11];
    const float* b5 = (const float*)d_in[12];
    float* out = (float*)d_out;

    int n = in_sizes[0] / 3;      // 100000
    int E = in_sizes[2] / 2;      // 1600000

    (void)n_in;
    (void)out_size;

    const int EDGE_SMEM = 2 * 128 * LDW * 2;   // 69632
    const int NODE_SMEM = 3 * 128 * LDW * 2;   // 104448
    cudaFuncSetAttribute(k_edge, cudaFuncAttributeMaxDynamicSharedMemorySize, EDGE_SMEM);
    cudaFuncSetAttribute(k_node_post, cudaFuncAttributeMaxDynamicSharedMemorySize, NODE_SMEM);

    int gpre = (n * HID + 255) / 256;
    k_node_pre<<<gpre, 256>>>(x, w1, b1, n);
    k_wconv<<<96, 256>>>(w2, w3, w4);

    int ge = (E + 255) / 256;
    k_hist<<<ge, 256>>>(ei, E);
    int nb = (n + 1023) / 1024;
    k_scan1<<<nb, 1024>>>(n);
    k_scan2<<<1, 32>>>(nb);
    k_scan3<<<(n + 255) / 256, 256>>>(n);
    k_scatter<<<ge, 256>>>(ei, E);

    int gedge = (E + TE - 1) / TE;
    k_edge<<<gedge, 256, EDGE_SMEM>>>(E, b2);

    int gnode = (n + 127) / 128;
    k_node_post<<<gnode, 256, NODE_SMEM>>>(pos, b3, b4, w5, b5, out, n);
}

// round 14
// speedup vs baseline: 10.3225x; 1.0644x over previous
#include <cuda_runtime.h>
#include <cuda_bf16.h>
#include <cstdint>
#include <math.h>

#define HID   128
#define NMAX  100000
#define EMAX  1600000
#define TE    128    // edges per tile in edge kernel
#define LDW   136    // bf16 row stride in smem (272B, 16B-aligned rows)

typedef unsigned long long ull;
typedef unsigned int u32;

// Scratch (static device globals — no runtime allocation).
__device__ __nv_bfloat16 g_Abf[(size_t)NMAX * HID];  // per-node dst term (bf16)
__device__ __nv_bfloat16 g_Bbf[(size_t)NMAX * HID];  // per-node src term (bf16)
__device__ __nv_bfloat16 g_w2bf[HID * HID];          // weights in bf16 [k][c]
__device__ __nv_bfloat16 g_w3bf[HID * HID];
__device__ __nv_bfloat16 g_w4bf[HID * HID];
__device__ int   g_AGG[(size_t)NMAX * HID]; // relu(segment_max) as float bits
__device__ int   g_cnt[NMAX];               // per-dst degree
__device__ int   g_off[NMAX];               // block-local exclusive offsets (cursors)
__device__ int   g_bsum[128];               // per-scan-block totals (scanned)
__device__ int2  g_sedge[EMAX];             // (src, dst) sorted by dst

// ---- bf16 helpers ----------------------------------------------------------
__device__ __forceinline__ u32 smaddr(const void* p) {
    return (u32)__cvta_generic_to_shared(p);
}
__device__ __forceinline__ void ldsm_x4(u32* r, u32 a) {
    asm volatile("ldmatrix.sync.aligned.m8n8.x4.shared.b16 {%0,%1,%2,%3}, [%4];"
        : "=r"(r[0]), "=r"(r[1]), "=r"(r[2]), "=r"(r[3]) : "r"(a));
}
__device__ __forceinline__ void ldsm_x4_t(u32* r, u32 a) {
    asm volatile("ldmatrix.sync.aligned.m8n8.x4.trans.shared.b16 {%0,%1,%2,%3}, [%4];"
        : "=r"(r[0]), "=r"(r[1]), "=r"(r[2]), "=r"(r[3]) : "r"(a));
}
__device__ __forceinline__ void mma16816(float* c, const u32* a, u32 b0, u32 b1) {
    asm volatile("mma.sync.aligned.m16n8k16.row.col.f32.bf16.bf16.f32 "
        "{%0,%1,%2,%3}, {%4,%5,%6,%7}, {%8,%9}, {%0,%1,%2,%3};"
        : "+f"(c[0]), "+f"(c[1]), "+f"(c[2]), "+f"(c[3])
        : "r"(a[0]), "r"(a[1]), "r"(a[2]), "r"(a[3]), "r"(b0), "r"(b1));
}
__device__ __forceinline__ u32 f2bf2(float lo, float hi) {
    __nv_bfloat162 h2 = __floats2bfloat162_rn(lo, hi);
    return *reinterpret_cast<u32*>(&h2);
}
__device__ __forceinline__ u32 hadd_relu2(u32 ua, u32 ub) {
    __nv_bfloat162 a = *reinterpret_cast<__nv_bfloat162*>(&ua);
    __nv_bfloat162 b = *reinterpret_cast<__nv_bfloat162*>(&ub);
    u32 uz = 0u;
    __nv_bfloat162 z = *reinterpret_cast<__nv_bfloat162*>(&uz);
    __nv_bfloat162 r = __hmax2(__hadd2(a, b), z);
    return *reinterpret_cast<u32*>(&r);
}
__device__ __forceinline__ u32 hmax2u(u32 ua, u32 ub) {
    __nv_bfloat162 a = *reinterpret_cast<__nv_bfloat162*>(&ua);
    __nv_bfloat162 b = *reinterpret_cast<__nv_bfloat162*>(&ub);
    __nv_bfloat162 r = __hmax2(a, b);
    return *reinterpret_cast<u32*>(&r);
}

// ---------------------------------------------------------------------------
// K1: per-node layer-1 terms (bf16), vectorized 4 channels/thread.
// Also zeros AGG (uint4) and degree counters.
// ---------------------------------------------------------------------------
__global__ void k_node_pre(const float* __restrict__ x,
                           const float* __restrict__ w1,
                           const float* __restrict__ b1, int n)
{
    int idx = blockIdx.x * 256 + threadIdx.x;
    if (idx >= n * 32) return;
    int i  = idx >> 5;          // node
    int q  = idx & 31;
    int c4 = q * 4;             // channel quad
    float x0 = x[i*3+0], x1 = x[i*3+1], x2 = x[i*3+2];
    float4 w0 = *(const float4*)(w1 + 0*HID + c4);
    float4 w1r = *(const float4*)(w1 + 1*HID + c4);
    float4 w2r = *(const float4*)(w1 + 2*HID + c4);
    float4 w3r = *(const float4*)(w1 + 3*HID + c4);
    float4 w4r = *(const float4*)(w1 + 4*HID + c4);
    float4 w5r = *(const float4*)(w1 + 5*HID + c4);
    float4 bb  = *(const float4*)(b1 + c4);

    float B0 = x0*w3r.x + x1*w4r.x + x2*w5r.x;
    float B1 = x0*w3r.y + x1*w4r.y + x2*w5r.y;
    float B2 = x0*w3r.z + x1*w4r.z + x2*w5r.z;
    float B3 = x0*w3r.w + x1*w4r.w + x2*w5r.w;
    float A0 = x0*(w0.x - w3r.x) + x1*(w1r.x - w4r.x) + x2*(w2r.x - w5r.x) + bb.x;
    float A1 = x0*(w0.y - w3r.y) + x1*(w1r.y - w4r.y) + x2*(w2r.y - w5r.y) + bb.y;
    float A2 = x0*(w0.z - w3r.z) + x1*(w1r.z - w4r.z) + x2*(w2r.z - w5r.z) + bb.z;
    float A3 = x0*(w0.w - w3r.w) + x1*(w1r.w - w4r.w) + x2*(w2r.w - w5r.w) + bb.w;

    size_t base = (size_t)i * HID + c4;
    uint2 av, bv;
    av.x = f2bf2(A0, A1); av.y = f2bf2(A2, A3);
    bv.x = f2bf2(B0, B1); bv.y = f2bf2(B2, B3);
    *(uint2*)(g_Abf + base) = av;
    *(uint2*)(g_Bbf + base) = bv;
    *(uint4*)(g_AGG + base) = make_uint4(0u, 0u, 0u, 0u);
    if (q == 0) g_cnt[i] = 0;
}

// ---------------------------------------------------------------------------
// K2: weight preconvert (w2,w3,w4 -> bf16) + dst-degree histogram (merged).
// Safe: g_cnt zeroed by k_node_pre, which completes first.
// ---------------------------------------------------------------------------
__global__ void k_wconv_hist(const float* __restrict__ w2,
                             const float* __restrict__ w3,
                             const float* __restrict__ w4,
                             const int* __restrict__ ei, int E)
{
    int i = blockIdx.x * 256 + threadIdx.x;
    const int P = HID * HID / 2;              // 8192
    if (i < P) {
        float2 v = ((const float2*)w2)[i];
        ((u32*)g_w2bf)[i] = f2bf2(v.x, v.y);
    } else if (i < 2*P) {
        float2 v = ((const float2*)w3)[i - P];
        ((u32*)g_w3bf)[i - P] = f2bf2(v.x, v.y);
    } else if (i < 3*P) {
        float2 v = ((const float2*)w4)[i - 2*P];
        ((u32*)g_w4bf)[i - 2*P] = f2bf2(v.x, v.y);
    }
    if (i < E) atomicAdd(&g_cnt[ei[E + i]], 1);
}

// ---------------------------------------------------------------------------
// S2a: per-block exclusive scan (1024-chunks) + block totals.
// ---------------------------------------------------------------------------
__global__ void __launch_bounds__(1024, 1) k_scan1(int n)
{
    __shared__ int wsum[32];
    int tid  = threadIdx.x;
    int lane = tid & 31;
    int w    = tid >> 5;
    int i = blockIdx.x * 1024 + tid;
    int v = (i < n) ? g_cnt[i] : 0;
    int xv = v;
    #pragma unroll
    for (int off = 1; off < 32; off <<= 1) {
        int y = __shfl_up_sync(0xffffffffu, xv, off);
        if (lane >= off) xv += y;
    }
    if (lane == 31) wsum[w] = xv;
    __syncthreads();
    if (w == 0) {
        int t = wsum[lane];
        #pragma unroll
        for (int off = 1; off < 32; off <<= 1) {
            int y = __shfl_up_sync(0xffffffffu, t, off);
            if (lane >= off) t += y;
        }
        wsum[lane] = t;
    }
    __syncthreads();
    int woff = (w > 0) ? wsum[w - 1] : 0;
    if (i < n) g_off[i] = woff + xv - v;       // block-local exclusive
    if (tid == 0) g_bsum[blockIdx.x] = wsum[31];
}

// ---------------------------------------------------------------------------
// S2b: one-warp exclusive scan of block totals (nb <= 128).
// ---------------------------------------------------------------------------
__global__ void k_scan2(int nb)
{
    int lane = threadIdx.x;
    int carry = 0;
    for (int base = 0; base < nb; base += 32) {
        int i = base + lane;
        int v = (i < nb) ? g_bsum[i] : 0;
        int xv = v;
        #pragma unroll
        for (int off = 1; off < 32; off <<= 1) {
            int y = __shfl_up_sync(0xffffffffu, xv, off);
            if (lane >= off) xv += y;
        }
        if (i < nb) g_bsum[i] = carry + xv - v;
        carry += __shfl_sync(0xffffffffu, xv, 31);
    }
}

// ---------------------------------------------------------------------------
// S3: scatter edges into dst-sorted order (block offset folded in here).
// ---------------------------------------------------------------------------
__global__ void k_scatter(const int* __restrict__ ei, int E)
{
    int e = blockIdx.x * 256 + threadIdx.x;
    if (e < E) {
        int s = ei[e];
        int d = ei[E + e];
        int p = atomicAdd(&g_off[d], 1) + g_bsum[d >> 10];
        g_sedge[p] = make_int2(s, d);
    }
}

// ---------------------------------------------------------------------------
// K2: bf16 mma.sync edge kernel over dst-sorted edges (R11-proven).
// smem: sw2 bf16 [128][LDW]  |  sa bf16 [128][LDW] (h-tile overlays sa as bf16x2)
// ---------------------------------------------------------------------------
__global__ void __launch_bounds__(256, 2)
k_edge(int E, const float* __restrict__ b2)
{
    extern __shared__ char smraw[];
    __nv_bfloat16* sw2 = (__nv_bfloat16*)smraw;
    __nv_bfloat16* sa  = (__nv_bfloat16*)(smraw + 128 * LDW * 2);
    u32*           shu = (u32*)sa;            // h-tile overlay
    __shared__ int sdst[TE];

    int tid = threadIdx.x;
    int tile0 = blockIdx.x * TE;

    {
        const uint4* gv = (const uint4*)g_w2bf;
        #pragma unroll
        for (int it = 0; it < 8; it++) {
            int idx = tid + it * 256;
            int k    = idx >> 4;
            int col8 = (idx & 15) * 8;
            *(uint4*)(sw2 + k * LDW + col8) = gv[idx];
        }
    }

    {
        int e  = tid >> 1;
        int hf = tid & 1;
        int eg = tile0 + e;
        if (eg < E) {
            int2 sd = g_sedge[eg];
            if (hf == 0) sdst[e] = sd.y;
            const uint4* Av = (const uint4*)(g_Abf + (size_t)sd.y * HID) + hf*8;
            const uint4* Bv = (const uint4*)(g_Bbf + (size_t)sd.x * HID) + hf*8;
            #pragma unroll
            for (int j = 0; j < 8; j++) {
                uint4 a = Av[j];
                uint4 b = Bv[j];
                uint4 r;
                r.x = hadd_relu2(a.x, b.x);
                r.y = hadd_relu2(a.y, b.y);
                r.z = hadd_relu2(a.z, b.z);
                r.w = hadd_relu2(a.w, b.w);
                *(uint4*)(sa + e * LDW + hf*64 + j*8) = r;
            }
        } else {
            if (hf == 0) sdst[e] = -1;
            uint4 z = make_uint4(0u, 0u, 0u, 0u);
            #pragma unroll
            for (int j = 0; j < 8; j++)
                *(uint4*)(sa + e * LDW + hf*64 + j*8) = z;
        }
    }
    __syncthreads();

    int lane = tid & 31;
    int wid  = tid >> 5;
    int e0   = (wid >> 1) * 32;
    int n0w  = (wid & 1) * 64;

    float acc[2][8][4];
    #pragma unroll
    for (int m = 0; m < 2; m++) {
        #pragma unroll
        for (int t = 0; t < 8; t++) {
            #pragma unroll
            for (int i = 0; i < 4; i++) acc[m][t][i] = 0.f;
        }
    }

    int rsel = lane & 15;
    int csel = (lane >> 4) << 3;

    #pragma unroll
    for (int k0 = 0; k0 < HID; k0 += 16) {
        u32 A0[4];
        u32 A1[4];
        ldsm_x4(A0, smaddr(sa + (e0 +      rsel) * LDW + k0 + csel));
        ldsm_x4(A1, smaddr(sa + (e0 + 16 + rsel) * LDW + k0 + csel));
        #pragma unroll
        for (int t = 0; t < 4; t++) {
            u32 Bf[4];
            ldsm_x4_t(Bf, smaddr(sw2 + (k0 + rsel) * LDW + n0w + t*16 + csel));
            mma16816(acc[0][2*t+0], A0, Bf[0], Bf[1]);
            mma16816(acc[0][2*t+1], A0, Bf[2], Bf[3]);
            mma16816(acc[1][2*t+0], A1, Bf[0], Bf[1]);
            mma16816(acc[1][2*t+1], A1, Bf[2], Bf[3]);
        }
    }

    __syncthreads();

    {
        int r0 = lane >> 2;
        int cq = (lane & 3) * 2;
        #pragma unroll
        for (int m = 0; m < 2; m++) {
            int rbase = e0 + m*16 + r0;
            #pragma unroll
            for (int t = 0; t < 8; t++) {
                int cp = (n0w + t*8 + cq) >> 1;
                shu[rbase       * (LDW/2) + cp] = f2bf2(acc[m][t][0], acc[m][t][1]);
                shu[(rbase + 8) * (LDW/2) + cp] = f2bf2(acc[m][t][2], acc[m][t][3]);
            }
        }
    }
    __syncthreads();

    {
        int p  = tid & 63;
        int eb = (tid >> 6) * 32;
        float2 bb = *(const float2*)(b2 + 2*p);
        int prev = sdst[eb];
        u32 mx = shu[eb * (LDW/2) + p];
        #pragma unroll 4
        for (int j = 1; j < 32; j++) {
            int d2 = sdst[eb + j];
            u32 v  = shu[(eb + j) * (LDW/2) + p];
            if (d2 != prev) {
                if (prev >= 0) {
                    float2 f = __bfloat1622float2(*reinterpret_cast<__nv_bfloat162*>(&mx));
                    atomicMax(g_AGG + (size_t)prev * HID + 2*p,
                              __float_as_int(fmaxf(f.x + bb.x, 0.f)));
                    atomicMax(g_AGG + (size_t)prev * HID + 2*p + 1,
                              __float_as_int(fmaxf(f.y + bb.y, 0.f)));
                }
                prev = d2;
                mx = v;
            } else {
                mx = hmax2u(mx, v);
            }
        }
        if (prev >= 0) {
            float2 f = __bfloat1622float2(*reinterpret_cast<__nv_bfloat162*>(&mx));
            atomicMax(g_AGG + (size_t)prev * HID + 2*p,
                      __float_as_int(fmaxf(f.x + bb.x, 0.f)));
            atomicMax(g_AGG + (size_t)prev * HID + 2*p + 1,
                      __float_as_int(fmaxf(f.y + bb.y, 0.f)));
        }
    }
}

// ---------------------------------------------------------------------------
// K3: bf16 mma.sync node tail (R11-proven).
// ---------------------------------------------------------------------------
__global__ void __launch_bounds__(256, 2)
k_node_post(const float* __restrict__ pos,
            const float* __restrict__ b3, const float* __restrict__ b4,
            const float* __restrict__ w5, const float* __restrict__ b5,
            float* __restrict__ out, int n)
{
    extern __shared__ char smraw2[];
    __nv_bfloat16* sw3 = (__nv_bfloat16*)smraw2;
    __nv_bfloat16* sw4 = sw3 + 128 * LDW;
    __nv_bfloat16* sa  = sw4 + 128 * LDW;
    u32*           sau = (u32*)sa;
    __shared__ float sw5[HID * 3];

    int tid = threadIdx.x;
    int n0 = blockIdx.x * 128;

    {
        const uint4* g3 = (const uint4*)g_w3bf;
        const uint4* g4 = (const uint4*)g_w4bf;
        #pragma unroll
        for (int it = 0; it < 8; it++) {
            int idx = tid + it * 256;
            int k    = idx >> 4;
            int col8 = (idx & 15) * 8;
            *(uint4*)(sw3 + k * LDW + col8) = g3[idx];
            *(uint4*)(sw4 + k * LDW + col8) = g4[idx];
        }
        if (tid < 192) ((float2*)sw5)[tid] = ((const float2*)w5)[tid];
    }

    {
        int r  = tid >> 1;
        int hf = tid & 1;
        int node = n0 + r;
        if (node < n) {
            const float4* Gv = (const float4*)((const float*)g_AGG + (size_t)node * HID) + hf*16;
            #pragma unroll
            for (int j = 0; j < 8; j++) {
                float4 a = Gv[2*j];
                float4 b = Gv[2*j + 1];
                uint4 rr;
                rr.x = f2bf2(a.x, a.y);
                rr.y = f2bf2(a.z, a.w);
                rr.z = f2bf2(b.x, b.y);
                rr.w = f2bf2(b.z, b.w);
                *(uint4*)(sa + r * LDW + hf*64 + j*8) = rr;
            }
        } else {
            uint4 z = make_uint4(0u, 0u, 0u, 0u);
            #pragma unroll
            for (int j = 0; j < 8; j++)
                *(uint4*)(sa + r * LDW + hf*64 + j*8) = z;
        }
    }
    __syncthreads();

    int lane = tid & 31;
    int wid  = tid >> 5;
    int e0   = (wid >> 1) * 32;
    int n0w  = (wid & 1) * 64;
    int rsel = lane & 15;
    int csel = (lane >> 4) << 3;
    int r0   = lane >> 2;
    int cq   = (lane & 3) * 2;

    float acc[2][8][4];

    #pragma unroll
    for (int m = 0; m < 2; m++) {
        #pragma unroll
        for (int t = 0; t < 8; t++) {
            #pragma unroll
            for (int i = 0; i < 4; i++) acc[m][t][i] = 0.f;
        }
    }
    #pragma unroll
    for (int k0 = 0; k0 < HID; k0 += 16) {
        u32 A0[4];
        u32 A1[4];
        ldsm_x4(A0, smaddr(sa + (e0 +      rsel) * LDW + k0 + csel));
        ldsm_x4(A1, smaddr(sa + (e0 + 16 + rsel) * LDW + k0 + csel));
        #pragma unroll
        for (int t = 0; t < 4; t++) {
            u32 Bf[4];
            ldsm_x4_t(Bf, smaddr(sw3 + (k0 + rsel) * LDW + n0w + t*16 + csel));
            mma16816(acc[0][2*t+0], A0, Bf[0], Bf[1]);
            mma16816(acc[0][2*t+1], A0, Bf[2], Bf[3]);
            mma16816(acc[1][2*t+0], A1, Bf[0], Bf[1]);
            mma16816(acc[1][2*t+1], A1, Bf[2], Bf[3]);
        }
    }
    __syncthreads();

    #pragma unroll
    for (int m = 0; m < 2; m++) {
        int rbase = e0 + m*16 + r0;
        #pragma unroll
        for (int t = 0; t < 8; t++) {
            int c = n0w + t*8 + cq;
            float bb0 = b3[c];
            float bb1 = b3[c+1];
            sau[rbase       * (LDW/2) + (c >> 1)] = f2bf2(acc[m][t][0] + bb0, acc[m][t][1] + bb1);
            sau[(rbase + 8) * (LDW/2) + (c >> 1)] = f2bf2(acc[m][t][2] + bb0, acc[m][t][3] + bb1);
        }
    }
    __syncthreads();

    #pragma unroll
    for (int m = 0; m < 2; m++) {
        #pragma unroll
        for (int t = 0; t < 8; t++) {
            #pragma unroll
            for (int i = 0; i < 4; i++) acc[m][t][i] = 0.f;
        }
    }
    #pragma unroll
    for (int k0 = 0; k0 < HID; k0 += 16) {
        u32 A0[4];
        u32 A1[4];
        ldsm_x4(A0, smaddr(sa + (e0 +      rsel) * LDW + k0 + csel));
        ldsm_x4(A1, smaddr(sa + (e0 + 16 + rsel) * LDW + k0 + csel));
        #pragma unroll
        for (int t = 0; t < 4; t++) {
            u32 Bf[4];
            ldsm_x4_t(Bf, smaddr(sw4 + (k0 + rsel) * LDW + n0w + t*16 + csel));
            mma16816(acc[0][2*t+0], A0, Bf[0], Bf[1]);
            mma16816(acc[0][2*t+1], A0, Bf[2], Bf[3]);
            mma16816(acc[1][2*t+0], A1, Bf[0], Bf[1]);
            mma16816(acc[1][2*t+1], A1, Bf[2], Bf[3]);
        }
    }
    __syncthreads();

    #pragma unroll
    for (int m = 0; m < 2; m++) {
        int rbase = e0 + m*16 + r0;
        #pragma unroll
        for (int t = 0; t < 8; t++) {
            int c = n0w + t*8 + cq;
            float bb0 = b4[c];
            float bb1 = b4[c+1];
            sau[rbase       * (LDW/2) + (c >> 1)] =
                f2bf2(fmaxf(acc[m][t][0] + bb0, 0.f), fmaxf(acc[m][t][1] + bb1, 0.f));
            sau[(rbase + 8) * (LDW/2) + (c >> 1)] =
                f2bf2(fmaxf(acc[m][t][2] + bb0, 0.f), fmaxf(acc[m][t][3] + bb1, 0.f));
        }
    }
    __syncthreads();

    {
        int r  = tid >> 1;
        int hf = tid & 1;
        float pd0 = 0.f, pd1 = 0.f, pd2 = 0.f;
        const u32* rowp = sau + r * (LDW/2) + hf*32;
        #pragma unroll 8
        for (int j = 0; j < 32; j++) {
            u32 uv = rowp[j];
            float2 f = __bfloat1622float2(*reinterpret_cast<__nv_bfloat162*>(&uv));
            int c = hf*64 + 2*j;
            pd0 = fmaf(f.x, sw5[c*3+0], pd0);
            pd1 = fmaf(f.x, sw5[c*3+1], pd1);
            pd2 = fmaf(f.x, sw5[c*3+2], pd2);
            pd0 = fmaf(f.y, sw5[c*3+3], pd0);
            pd1 = fmaf(f.y, sw5[c*3+4], pd1);
            pd2 = fmaf(f.y, sw5[c*3+5], pd2);
        }
        pd0 += __shfl_xor_sync(0xffffffffu, pd0, 1);
        pd1 += __shfl_xor_sync(0xffffffffu, pd1, 1);
        pd2 += __shfl_xor_sync(0xffffffffu, pd2, 1);
        int node = n0 + r;
        if (hf == 0 && node < n) {
            out[node*3 + 0] = pos[node*3 + 0] + 0.1f * tanhf(pd0 + b5[0]);
            out[node*3 + 1] = pos[node*3 + 1] + 0.1f * tanhf(pd1 + b5[1]);
            out[node*3 + 2] = pos[node*3 + 2] + 0.1f * tanhf(pd2 + b5[2]);
        }
    }
}

// ---------------------------------------------------------------------------
extern "C" void kernel_launch(void* const* d_in, const int* in_sizes, int n_in,
                              void* d_out, int out_size)
{
    const float* x   = (const float*)d_in[0];
    const float* pos = (const float*)d_in[1];
    const int*   ei  = (const int*)d_in[2];   // int32
    const float* w1 = (const float*)d_in[3];
    const float* b1 = (const float*)d_in[4];
    const float* w2 = (const float*)d_in[5];
    const float* b2 = (const float*)d_in[6];
    const float* w3 = (const float*)d_in[7];
    const float* b3 = (const float*)d_in[8];
    const float* w4 = (const float*)d_in[9];
    const float* b4 = (const float*)d_in[10];
    const float* w5 = (const float*)d_in[11];
    const float* b5 = (const float*)d_in[12];
    float* out = (float*)d_out;

    int n = in_sizes[0] / 3;      // 100000
    int E = in_sizes[2] / 2;      // 1600000

    (void)n_in;
    (void)out_size;

    const int EDGE_SMEM = 2 * 128 * LDW * 2;   // 69632
    const int NODE_SMEM = 3 * 128 * LDW * 2;   // 104448
    cudaFuncSetAttribute(k_edge, cudaFuncAttributeMaxDynamicSharedMemorySize, EDGE_SMEM);
    cudaFuncSetAttribute(k_node_post, cudaFuncAttributeMaxDynamicSharedMemorySize, NODE_SMEM);

    // launch 1: node pre (zeros g_cnt)
    int gpre = (n * 32 + 255) / 256;
    k_node_pre<<<gpre, 256>>>(x, w1, b1, n);

    // launch 2: weight convert + histogram (needs g_cnt zeroed)
    int ge = (E + 255) / 256;
    k_wconv_hist<<<ge, 256>>>(w2, w3, w4, ei, E);

    // launches 3-4: scan
    int nb = (n + 1023) / 1024;
    k_scan1<<<nb, 1024>>>(n);
    k_scan2<<<1, 32>>>(nb);

    // launch 5: scatter (folds block offsets)
    k_scatter<<<ge, 256>>>(ei, E);

    // launch 6: edge kernel (ncu -s 5 profiles this one)
    int gedge = (E + TE - 1) / TE;
    k_edge<<<gedge, 256, EDGE_SMEM>>>(E, b2);

    // launch 7: node tail
    int gnode = (n + 127) / 128;
    k_node_post<<<gnode, 256, NODE_SMEM>>>(pos, b3, b4, w5, b5, out, n);
}

// round 15
// speedup vs baseline: 10.7839x; 1.0447x over previous
#include <cuda_runtime.h>
#include <cuda_bf16.h>
#include <cstdint>
#include <math.h>

#define HID   128
#define NMAX  100000
#define EMAX  1600000
#define TE    128    // edges per tile in edge kernel
#define LDW   136    // bf16 row stride in smem (272B, 16B-aligned rows)

typedef unsigned long long ull;
typedef unsigned int u32;

// Scratch (static device globals — no runtime allocation).
// g_cnt / g_done rely on static zero-init; both are restored to 0 by k_scan12
// each run, so every graph replay sees the same initial state (deterministic).
__device__ __nv_bfloat16 g_Abf[(size_t)NMAX * HID];  // per-node dst term (bf16)
__device__ __nv_bfloat16 g_Bbf[(size_t)NMAX * HID];  // per-node src term (bf16)
__device__ __nv_bfloat16 g_w2bf[HID * HID];          // weights in bf16 [k][c]
__device__ __nv_bfloat16 g_w3bf[HID * HID];
__device__ __nv_bfloat16 g_w4bf[HID * HID];
__device__ int   g_AGG[(size_t)NMAX * HID]; // relu(segment_max) as float bits
__device__ int   g_cnt[NMAX];               // per-dst degree (zero at kernel entry)
__device__ int   g_off[NMAX];               // block-local exclusive offsets (cursors)
__device__ int   g_bsum[128];               // per-scan-block totals (scanned)
__device__ int   g_done;                    // scan completion counter (self-reset)
__device__ int2  g_sedge[EMAX];             // (src, dst) sorted by dst

// ---- bf16 helpers ----------------------------------------------------------
__device__ __forceinline__ u32 smaddr(const void* p) {
    return (u32)__cvta_generic_to_shared(p);
}
__device__ __forceinline__ void ldsm_x4(u32* r, u32 a) {
    asm volatile("ldmatrix.sync.aligned.m8n8.x4.shared.b16 {%0,%1,%2,%3}, [%4];"
        : "=r"(r[0]), "=r"(r[1]), "=r"(r[2]), "=r"(r[3]) : "r"(a));
}
__device__ __forceinline__ void ldsm_x4_t(u32* r, u32 a) {
    asm volatile("ldmatrix.sync.aligned.m8n8.x4.trans.shared.b16 {%0,%1,%2,%3}, [%4];"
        : "=r"(r[0]), "=r"(r[1]), "=r"(r[2]), "=r"(r[3]) : "r"(a));
}
__device__ __forceinline__ void mma16816(float* c, const u32* a, u32 b0, u32 b1) {
    asm volatile("mma.sync.aligned.m16n8k16.row.col.f32.bf16.bf16.f32 "
        "{%0,%1,%2,%3}, {%4,%5,%6,%7}, {%8,%9}, {%0,%1,%2,%3};"
        : "+f"(c[0]), "+f"(c[1]), "+f"(c[2]), "+f"(c[3])
        : "r"(a[0]), "r"(a[1]), "r"(a[2]), "r"(a[3]), "r"(b0), "r"(b1));
}
__device__ __forceinline__ u32 f2bf2(float lo, float hi) {
    __nv_bfloat162 h2 = __floats2bfloat162_rn(lo, hi);
    return *reinterpret_cast<u32*>(&h2);
}
__device__ __forceinline__ u32 hadd_relu2(u32 ua, u32 ub) {
    __nv_bfloat162 a = *reinterpret_cast<__nv_bfloat162*>(&ua);
    __nv_bfloat162 b = *reinterpret_cast<__nv_bfloat162*>(&ub);
    u32 uz = 0u;
    __nv_bfloat162 z = *reinterpret_cast<__nv_bfloat162*>(&uz);
    __nv_bfloat162 r = __hmax2(__hadd2(a, b), z);
    return *reinterpret_cast<u32*>(&r);
}
__device__ __forceinline__ u32 hmax2u(u32 ua, u32 ub) {
    __nv_bfloat162 a = *reinterpret_cast<__nv_bfloat162*>(&ua);
    __nv_bfloat162 b = *reinterpret_cast<__nv_bfloat162*>(&ub);
    __nv_bfloat162 r = __hmax2(a, b);
    return *reinterpret_cast<u32*>(&r);
}

// ---------------------------------------------------------------------------
// K0 (launch 0): merged init.
//  - per-node layer-1 terms (bf16, 4 channels/thread) + zero AGG
//  - w2/w3/w4 -> bf16
//  - dst-degree histogram (g_cnt is zero on entry: static init / scan restore)
// ---------------------------------------------------------------------------
__global__ void k_init(const float* __restrict__ x,
                       const float* __restrict__ w1,
                       const float* __restrict__ b1,
                       const float* __restrict__ w2,
                       const float* __restrict__ w3,
                       const float* __restrict__ w4,
                       const int* __restrict__ ei, int n, int E)
{
    int idx = blockIdx.x * 256 + threadIdx.x;

    if (idx < n * 32) {
        int i  = idx >> 5;          // node
        int q  = idx & 31;
        int c4 = q * 4;             // channel quad
        float x0 = x[i*3+0], x1 = x[i*3+1], x2 = x[i*3+2];
        float4 w0  = *(const float4*)(w1 + 0*HID + c4);
        float4 w1r = *(const float4*)(w1 + 1*HID + c4);
        float4 w2r = *(const float4*)(w1 + 2*HID + c4);
        float4 w3r = *(const float4*)(w1 + 3*HID + c4);
        float4 w4r = *(const float4*)(w1 + 4*HID + c4);
        float4 w5r = *(const float4*)(w1 + 5*HID + c4);
        float4 bb  = *(const float4*)(b1 + c4);

        float B0 = x0*w3r.x + x1*w4r.x + x2*w5r.x;
        float B1 = x0*w3r.y + x1*w4r.y + x2*w5r.y;
        float B2 = x0*w3r.z + x1*w4r.z + x2*w5r.z;
        float B3 = x0*w3r.w + x1*w4r.w + x2*w5r.w;
        float A0 = x0*(w0.x - w3r.x) + x1*(w1r.x - w4r.x) + x2*(w2r.x - w5r.x) + bb.x;
        float A1 = x0*(w0.y - w3r.y) + x1*(w1r.y - w4r.y) + x2*(w2r.y - w5r.y) + bb.y;
        float A2 = x0*(w0.z - w3r.z) + x1*(w1r.z - w4r.z) + x2*(w2r.z - w5r.z) + bb.z;
        float A3 = x0*(w0.w - w3r.w) + x1*(w1r.w - w4r.w) + x2*(w2r.w - w5r.w) + bb.w;

        size_t base = (size_t)i * HID + c4;
        uint2 av, bv;
        av.x = f2bf2(A0, A1); av.y = f2bf2(A2, A3);
        bv.x = f2bf2(B0, B1); bv.y = f2bf2(B2, B3);
        *(uint2*)(g_Abf + base) = av;
        *(uint2*)(g_Bbf + base) = bv;
        *(uint4*)(g_AGG + base) = make_uint4(0u, 0u, 0u, 0u);
    }

    const int P = HID * HID / 2;              // 8192
    if (idx < P) {
        float2 v = ((const float2*)w2)[idx];
        ((u32*)g_w2bf)[idx] = f2bf2(v.x, v.y);
    } else if (idx < 2*P) {
        float2 v = ((const float2*)w3)[idx - P];
        ((u32*)g_w3bf)[idx - P] = f2bf2(v.x, v.y);
    } else if (idx < 3*P) {
        float2 v = ((const float2*)w4)[idx - 2*P];
        ((u32*)g_w4bf)[idx - 2*P] = f2bf2(v.x, v.y);
    }

    if (idx < E) atomicAdd(&g_cnt[ei[E + idx]], 1);
}

// ---------------------------------------------------------------------------
// K1 (launch 1): scan. Per-block exclusive scan + last-block scans the block
// totals. Also restores g_cnt to 0 and g_done to 0 for the next replay.
// ---------------------------------------------------------------------------
__global__ void __launch_bounds__(1024, 1) k_scan12(int n, int nb)
{
    __shared__ int wsum[32];
    __shared__ int slast;
    int tid  = threadIdx.x;
    int lane = tid & 31;
    int w    = tid >> 5;
    int i = blockIdx.x * 1024 + tid;
    int v = (i < n) ? g_cnt[i] : 0;
    if (i < n) g_cnt[i] = 0;                   // restore for next replay
    int xv = v;
    #pragma unroll
    for (int off = 1; off < 32; off <<= 1) {
        int y = __shfl_up_sync(0xffffffffu, xv, off);
        if (lane >= off) xv += y;
    }
    if (lane == 31) wsum[w] = xv;
    __syncthreads();
    if (w == 0) {
        int t = wsum[lane];
        #pragma unroll
        for (int off = 1; off < 32; off <<= 1) {
            int y = __shfl_up_sync(0xffffffffu, t, off);
            if (lane >= off) t += y;
        }
        wsum[lane] = t;
    }
    __syncthreads();
    int woff = (w > 0) ? wsum[w - 1] : 0;
    if (i < n) g_off[i] = woff + xv - v;       // block-local exclusive
    if (tid == 0) g_bsum[blockIdx.x] = wsum[31];

    // last block scans g_bsum
    __threadfence();
    if (tid == 0) slast = (atomicAdd(&g_done, 1) == nb - 1) ? 1 : 0;
    __syncthreads();
    if (slast) {
        __threadfence();                       // acquire all g_bsum writes
        if (tid < 32) {
            int carry = 0;
            for (int base = 0; base < nb; base += 32) {
                int j = base + tid;
                int bv = (j < nb) ? g_bsum[j] : 0;
                int sx = bv;
                #pragma unroll
                for (int off = 1; off < 32; off <<= 1) {
                    int y = __shfl_up_sync(0xffffffffu, sx, off);
                    if (tid >= off) sx += y;
                }
                if (j < nb) g_bsum[j] = carry + sx - bv;
                carry += __shfl_sync(0xffffffffu, sx, 31);
            }
        }
        if (tid == 0) g_done = 0;              // reset for next replay
    }
}

// ---------------------------------------------------------------------------
// K2 (launch 2): scatter edges into dst-sorted order.
// ---------------------------------------------------------------------------
__global__ void k_scatter(const int* __restrict__ ei, int E)
{
    int e = blockIdx.x * 256 + threadIdx.x;
    if (e < E) {
        int s = ei[e];
        int d = ei[E + e];
        int p = atomicAdd(&g_off[d], 1) + g_bsum[d >> 10];
        g_sedge[p] = make_int2(s, d);
    }
}

// ---------------------------------------------------------------------------
// K3 (launch 3 — ncu profile slot): persistent bf16 mma.sync edge kernel.
// w2 loaded into smem ONCE per CTA; loop over 128-edge tiles.
// smem: sw2 bf16 [128][LDW] | sa bf16 [128][LDW] (h-tile overlays sa as bf16x2)
// ---------------------------------------------------------------------------
__global__ void __launch_bounds__(256, 2)
k_edge(int E, const float* __restrict__ b2)
{
    extern __shared__ char smraw[];
    __nv_bfloat16* sw2 = (__nv_bfloat16*)smraw;
    __nv_bfloat16* sa  = (__nv_bfloat16*)(smraw + 128 * LDW * 2);
    u32*           shu = (u32*)sa;            // h-tile overlay
    __shared__ int sdst[TE];

    int tid  = threadIdx.x;
    int lane = tid & 31;
    int wid  = tid >> 5;

    // load w2 once
    {
        const uint4* gv = (const uint4*)g_w2bf;
        #pragma unroll
        for (int it = 0; it < 8; it++) {
            int idx = tid + it * 256;
            int k    = idx >> 4;
            int col8 = (idx & 15) * 8;
            *(uint4*)(sw2 + k * LDW + col8) = gv[idx];
        }
    }
    __syncthreads();

    int e0   = (wid >> 1) * 32;
    int n0w  = (wid & 1) * 64;
    int rsel = lane & 15;
    int csel = (lane >> 4) << 3;
    int r0   = lane >> 2;
    int cq   = (lane & 3) * 2;

    int ntiles = (E + TE - 1) / TE;

    for (int tile = blockIdx.x; tile < ntiles; tile += gridDim.x) {
        int tile0 = tile * TE;

        // gather relu(A[dst]+B[src]) in packed bf16, 2 threads/edge
        {
            int e  = tid >> 1;
            int hf = tid & 1;
            int eg = tile0 + e;
            if (eg < E) {
                int2 sd = g_sedge[eg];
                if (hf == 0) sdst[e] = sd.y;
                const uint4* Av = (const uint4*)(g_Abf + (size_t)sd.y * HID) + hf*8;
                const uint4* Bv = (const uint4*)(g_Bbf + (size_t)sd.x * HID) + hf*8;
                #pragma unroll
                for (int j = 0; j < 8; j++) {
                    uint4 a = Av[j];
                    uint4 b = Bv[j];
                    uint4 r;
                    r.x = hadd_relu2(a.x, b.x);
                    r.y = hadd_relu2(a.y, b.y);
                    r.z = hadd_relu2(a.z, b.z);
                    r.w = hadd_relu2(a.w, b.w);
                    *(uint4*)(sa + e * LDW + hf*64 + j*8) = r;
                }
            } else {
                if (hf == 0) sdst[e] = -1;
                uint4 z = make_uint4(0u, 0u, 0u, 0u);
                #pragma unroll
                for (int j = 0; j < 8; j++)
                    *(uint4*)(sa + e * LDW + hf*64 + j*8) = z;
            }
        }
        __syncthreads();

        float acc[2][8][4];
        #pragma unroll
        for (int m = 0; m < 2; m++) {
            #pragma unroll
            for (int t = 0; t < 8; t++) {
                #pragma unroll
                for (int i = 0; i < 4; i++) acc[m][t][i] = 0.f;
            }
        }

        #pragma unroll
        for (int k0 = 0; k0 < HID; k0 += 16) {
            u32 A0[4];
            u32 A1[4];
            ldsm_x4(A0, smaddr(sa + (e0 +      rsel) * LDW + k0 + csel));
            ldsm_x4(A1, smaddr(sa + (e0 + 16 + rsel) * LDW + k0 + csel));
            #pragma unroll
            for (int t = 0; t < 4; t++) {
                u32 Bf[4];
                ldsm_x4_t(Bf, smaddr(sw2 + (k0 + rsel) * LDW + n0w + t*16 + csel));
                mma16816(acc[0][2*t+0], A0, Bf[0], Bf[1]);
                mma16816(acc[0][2*t+1], A0, Bf[2], Bf[3]);
                mma16816(acc[1][2*t+0], A1, Bf[0], Bf[1]);
                mma16816(acc[1][2*t+1], A1, Bf[2], Bf[3]);
            }
        }
        __syncthreads();   // all warps done reading sa before overlay

        // store h fragments as bf16x2 into shu [edge][64 pairs]
        #pragma unroll
        for (int m = 0; m < 2; m++) {
            int rbase = e0 + m*16 + r0;
            #pragma unroll
            for (int t = 0; t < 8; t++) {
                int cp = (n0w + t*8 + cq) >> 1;
                shu[rbase       * (LDW/2) + cp] = f2bf2(acc[m][t][0], acc[m][t][1]);
                shu[(rbase + 8) * (LDW/2) + cp] = f2bf2(acc[m][t][2], acc[m][t][3]);
            }
        }
        __syncthreads();

        // segmented max over dst-groups (packed bf16x2 channel pairs)
        {
            int p  = tid & 63;
            int eb = (tid >> 6) * 32;
            float2 bb = *(const float2*)(b2 + 2*p);
            int prev = sdst[eb];
            u32 mx = shu[eb * (LDW/2) + p];
            #pragma unroll 4
            for (int j = 1; j < 32; j++) {
                int d2 = sdst[eb + j];
                u32 v  = shu[(eb + j) * (LDW/2) + p];
                if (d2 != prev) {
                    if (prev >= 0) {
                        float2 f = __bfloat1622float2(*reinterpret_cast<__nv_bfloat162*>(&mx));
                        atomicMax(g_AGG + (size_t)prev * HID + 2*p,
                                  __float_as_int(fmaxf(f.x + bb.x, 0.f)));
                        atomicMax(g_AGG + (size_t)prev * HID + 2*p + 1,
                                  __float_as_int(fmaxf(f.y + bb.y, 0.f)));
                    }
                    prev = d2;
                    mx = v;
                } else {
                    mx = hmax2u(mx, v);
                }
            }
            if (prev >= 0) {
                float2 f = __bfloat1622float2(*reinterpret_cast<__nv_bfloat162*>(&mx));
                atomicMax(g_AGG + (size_t)prev * HID + 2*p,
                          __float_as_int(fmaxf(f.x + bb.x, 0.f)));
                atomicMax(g_AGG + (size_t)prev * HID + 2*p + 1,
                          __float_as_int(fmaxf(f.y + bb.y, 0.f)));
            }
        }
        __syncthreads();   // protect sa/shu + sdst before next tile
    }
}

// ---------------------------------------------------------------------------
// K4 (launch 4): bf16 mma.sync node tail (proven).
// ---------------------------------------------------------------------------
__global__ void __launch_bounds__(256, 2)
k_node_post(const float* __restrict__ pos,
            const float* __restrict__ b3, const float* __restrict__ b4,
            const float* __restrict__ w5, const float* __restrict__ b5,
            float* __restrict__ out, int n)
{
    extern __shared__ char smraw2[];
    __nv_bfloat16* sw3 = (__nv_bfloat16*)smraw2;
    __nv_bfloat16* sw4 = sw3 + 128 * LDW;
    __nv_bfloat16* sa  = sw4 + 128 * LDW;
    u32*           sau = (u32*)sa;
    __shared__ float sw5[HID * 3];

    int tid = threadIdx.x;
    int n0 = blockIdx.x * 128;

    {
        const uint4* g3 = (const uint4*)g_w3bf;
        const uint4* g4 = (const uint4*)g_w4bf;
        #pragma unroll
        for (int it = 0; it < 8; it++) {
            int idx = tid + it * 256;
            int k    = idx >> 4;
            int col8 = (idx & 15) * 8;
            *(uint4*)(sw3 + k * LDW + col8) = g3[idx];
            *(uint4*)(sw4 + k * LDW + col8) = g4[idx];
        }
        if (tid < 192) ((float2*)sw5)[tid] = ((const float2*)w5)[tid];
    }

    {
        int r  = tid >> 1;
        int hf = tid & 1;
        int node = n0 + r;
        if (node < n) {
            const float4* Gv = (const float4*)((const float*)g_AGG + (size_t)node * HID) + hf*16;
            #pragma unroll
            for (int j = 0; j < 8; j++) {
                float4 a = Gv[2*j];
                float4 b = Gv[2*j + 1];
                uint4 rr;
                rr.x = f2bf2(a.x, a.y);
                rr.y = f2bf2(a.z, a.w);
                rr.z = f2bf2(b.x, b.y);
                rr.w = f2bf2(b.z, b.w);
                *(uint4*)(sa + r * LDW + hf*64 + j*8) = rr;
            }
        } else {
            uint4 z = make_uint4(0u, 0u, 0u, 0u);
            #pragma unroll
            for (int j = 0; j < 8; j++)
                *(uint4*)(sa + r * LDW + hf*64 + j*8) = z;
        }
    }
    __syncthreads();

    int lane = tid & 31;
    int wid  = tid >> 5;
    int e0   = (wid >> 1) * 32;
    int n0w  = (wid & 1) * 64;
    int rsel = lane & 15;
    int csel = (lane >> 4) << 3;
    int r0   = lane >> 2;
    int cq   = (lane & 3) * 2;

    float acc[2][8][4];

    #pragma unroll
    for (int m = 0; m < 2; m++) {
        #pragma unroll
        for (int t = 0; t < 8; t++) {
            #pragma unroll
            for (int i = 0; i < 4; i++) acc[m][t][i] = 0.f;
        }
    }
    #pragma unroll
    for (int k0 = 0; k0 < HID; k0 += 16) {
        u32 A0[4];
        u32 A1[4];
        ldsm_x4(A0, smaddr(sa + (e0 +      rsel) * LDW + k0 + csel));
        ldsm_x4(A1, smaddr(sa + (e0 + 16 + rsel) * LDW + k0 + csel));
        #pragma unroll
        for (int t = 0; t < 4; t++) {
            u32 Bf[4];
            ldsm_x4_t(Bf, smaddr(sw3 + (k0 + rsel) * LDW + n0w + t*16 + csel));
            mma16816(acc[0][2*t+0], A0, Bf[0], Bf[1]);
            mma16816(acc[0][2*t+1], A0, Bf[2], Bf[3]);
            mma16816(acc[1][2*t+0], A1, Bf[0], Bf[1]);
            mma16816(acc[1][2*t+1], A1, Bf[2], Bf[3]);
        }
    }
    __syncthreads();

    #pragma unroll
    for (int m = 0; m < 2; m++) {
        int rbase = e0 + m*16 + r0;
        #pragma unroll
        for (int t = 0; t < 8; t++) {
            int c = n0w + t*8 + cq;
            float bb0 = b3[c];
            float bb1 = b3[c+1];
            sau[rbase       * (LDW/2) + (c >> 1)] = f2bf2(acc[m][t][0] + bb0, acc[m][t][1] + bb1);
            sau[(rbase + 8) * (LDW/2) + (c >> 1)] = f2bf2(acc[m][t][2] + bb0, acc[m][t][3] + bb1);
        }
    }
    __syncthreads();

    #pragma unroll
    for (int m = 0; m < 2; m++) {
        #pragma unroll
        for (int t = 0; t < 8; t++) {
            #pragma unroll
            for (int i = 0; i < 4; i++) acc[m][t][i] = 0.f;
        }
    }
    #pragma unroll
    for (int k0 = 0; k0 < HID; k0 += 16) {
        u32 A0[4];
        u32 A1[4];
        ldsm_x4(A0, smaddr(sa + (e0 +      rsel) * LDW + k0 + csel));
        ldsm_x4(A1, smaddr(sa + (e0 + 16 + rsel) * LDW + k0 + csel));
        #pragma unroll
        for (int t = 0; t < 4; t++) {
            u32 Bf[4];
            ldsm_x4_t(Bf, smaddr(sw4 + (k0 + rsel) * LDW + n0w + t*16 + csel));
            mma16816(acc[0][2*t+0], A0, Bf[0], Bf[1]);
            mma16816(acc[0][2*t+1], A0, Bf[2], Bf[3]);
            mma16816(acc[1][2*t+0], A1, Bf[0], Bf[1]);
            mma16816(acc[1][2*t+1], A1, Bf[2], Bf[3]);
        }
    }
    __syncthreads();

    #pragma unroll
    for (int m = 0; m < 2; m++) {
        int rbase = e0 + m*16 + r0;
        #pragma unroll
        for (int t = 0; t < 8; t++) {
            int c = n0w + t*8 + cq;
            float bb0 = b4[c];
            float bb1 = b4[c+1];
            sau[rbase       * (LDW/2) + (c >> 1)] =
                f2bf2(fmaxf(acc[m][t][0] + bb0, 0.f), fmaxf(acc[m][t][1] + bb1, 0.f));
            sau[(rbase + 8) * (LDW/2) + (c >> 1)] =
                f2bf2(fmaxf(acc[m][t][2] + bb0, 0.f), fmaxf(acc[m][t][3] + bb1, 0.f));
        }
    }
    __syncthreads();

    {
        int r  = tid >> 1;
        int hf = tid & 1;
        float pd0 = 0.f, pd1 = 0.f, pd2 = 0.f;
        const u32* rowp = sau + r * (LDW/2) + hf*32;
        #pragma unroll 8
        for (int j = 0; j < 32; j++) {
            u32 uv = rowp[j];
            float2 f = __bfloat1622float2(*reinterpret_cast<__nv_bfloat162*>(&uv));
            int c = hf*64 + 2*j;
            pd0 = fmaf(f.x, sw5[c*3+0], pd0);
            pd1 = fmaf(f.x, sw5[c*3+1], pd1);
            pd2 = fmaf(f.x, sw5[c*3+2], pd2);
            pd0 = fmaf(f.y, sw5[c*3+3], pd0);
            pd1 = fmaf(f.y, sw5[c*3+4], pd1);
            pd2 = fmaf(f.y, sw5[c*3+5], pd2);
        }
        pd0 += __shfl_xor_sync(0xffffffffu, pd0, 1);
        pd1 += __shfl_xor_sync(0xffffffffu, pd1, 1);
        pd2 += __shfl_xor_sync(0xffffffffu, pd2, 1);
        int node = n0 + r;
        if (hf == 0 && node < n) {
            out[node*3 + 0] = pos[node*3 + 0] + 0.1f * tanhf(pd0 + b5[0]);
            out[node*3 + 1] = pos[node*3 + 1] + 0.1f * tanhf(pd1 + b5[1]);
            out[node*3 + 2] = pos[node*3 + 2] + 0.1f * tanhf(pd2 + b5[2]);
        }
    }
}

// ---------------------------------------------------------------------------
extern "C" void kernel_launch(void* const* d_in, const int* in_sizes, int n_in,
                              void* d_out, int out_size)
{
    const float* x   = (const float*)d_in[0];
    const float* pos = (const float*)d_in[1];
    const int*   ei  = (const int*)d_in[2];   // int32
    const float* w1 = (const float*)d_in[3];
    const float* b1 = (const float*)d_in[4];
    const float* w2 = (const float*)d_in[5];
    const float* b2 = (const float*)d_in[6];
    const float* w3 = (const float*)d_in[7];
    const float* b3 = (const float*)d_in[8];
    const float* w4 = (const float*)d_in[9];
    const float* b4 = (const float*)d_in[10];
    const float* w5 = (const float*)d_in[11];
    const float* b5 = (const float*)d_in[12];
    float* out = (float*)d_out;

    int n = in_sizes[0] / 3;      // 100000
    int E = in_sizes[2] / 2;      // 1600000

    (void)n_in;
    (void)out_size;

    const int EDGE_SMEM = 2 * 128 * LDW * 2;   // 69632
    const int NODE_SMEM = 3 * 128 * LDW * 2;   // 104448
    cudaFuncSetAttribute(k_edge, cudaFuncAttributeMaxDynamicSharedMemorySize, EDGE_SMEM);
    cudaFuncSetAttribute(k_node_post, cudaFuncAttributeMaxDynamicSharedMemorySize, NODE_SMEM);

    // launch 0: merged init (pre + wconv + hist)
    int ginit = (n * 32 + 255) / 256;          // covers n*32 > E > 3P
    k_init<<<ginit, 256>>>(x, w1, b1, w2, w3, w4, ei, n, E);

    // launch 1: fused scan (also restores g_cnt/g_done for replay)
    int nb = (n + 1023) / 1024;
    k_scan12<<<nb, 1024>>>(n, nb);

    // launch 2: scatter
    k_scatter<<<(E + 255) / 256, 256>>>(ei, E);

    // launch 3: persistent edge kernel (ncu profile slot)
    k_edge<<<296, 256, EDGE_SMEM>>>(E, b2);

    // launch 4: node tail
    int gnode = (n + 127) / 128;
    k_node_post<<<gnode, 256, NODE_SMEM>>>(pos, b3, b4, w5, b5, out, n);
}